// round 2
// baseline (speedup 1.0000x reference)
#include <cuda_runtime.h>

// Problem constants
#define BB   32
#define SS   512
#define DDIM 512
#define HH   8
#define DK   64
#define MM   (BB * SS)     // 16384 tokens
#define DFFN 2048

// ---------------------------------------------------------------------------
// Scratch (device globals — allocation-free per harness rules)
// ---------------------------------------------------------------------------
__device__ float g_q  [MM * DDIM];
__device__ float g_k  [MM * DDIM];
__device__ float g_v  [MM * DDIM];
__device__ float g_nq [MM * HH];
__device__ float g_nk [MM * HH];
__device__ float g_att[MM * DDIM];
__device__ float g_t1 [MM * DDIM];
__device__ float g_h1 [MM * DDIM];
__device__ float g_ff [(size_t)MM * DFFN];
__device__ float g_t2 [MM * DDIM];

// ---------------------------------------------------------------------------
// SGEMM: C[M,N] = A[M,K] @ B[K,N] with fused epilogues.
//   EPI 0: C = acc
//   EPI 1: C = relu(acc + bias[n])
//   EPI 2: C = acc + bias[n] + res[m,n]
//   EPI 3: C = acc + res[m,n]
// BM=BN=128, BK=8, 256 threads, 8x8 per-thread tile, double-buffered smem.
// All dims assumed divisible (they are for this problem).
// ---------------------------------------------------------------------------
template <int EPI>
__global__ __launch_bounds__(256, 2)
void sgemm_k(const float* __restrict__ A, const float* __restrict__ B,
             float* __restrict__ C, int M, int N, int K,
             const float* __restrict__ bias, const float* __restrict__ res)
{
    __shared__ float As[2][8][128];   // As[buf][k][m]
    __shared__ float Bs[2][8][128];   // Bs[buf][k][n]

    const int tid = threadIdx.x;
    const int bm  = blockIdx.y;
    const int bn  = blockIdx.x;

    // A-tile load mapping: 128 rows x 8 k, 2 threads per row (4 k each)
    const int am = tid >> 1;          // 0..127
    const int ak = (tid & 1) * 4;     // 0 or 4
    // B-tile load mapping: 8 k-rows x 128 cols, 32 threads per row (float4)
    const int bk  = tid >> 5;         // 0..7
    const int bnn = (tid & 31) * 4;   // 0..124

    const float* Ag = A + (size_t)(bm * 128 + am) * K + ak;
    const float* Bg = B + (size_t)bk * N + bn * 128 + bnn;

    const int tx = tid & 15;          // 0..15  -> 8 cols
    const int ty = tid >> 4;          // 0..15  -> 8 rows

    // prologue: load k-block 0
    float4 a4 = *(const float4*)Ag;
    float4 b4 = *(const float4*)Bg;
    As[0][ak + 0][am] = a4.x;
    As[0][ak + 1][am] = a4.y;
    As[0][ak + 2][am] = a4.z;
    As[0][ak + 3][am] = a4.w;
    *(float4*)&Bs[0][bk][bnn] = b4;
    __syncthreads();

    float acc[8][8];
#pragma unroll
    for (int i = 0; i < 8; i++)
#pragma unroll
        for (int j = 0; j < 8; j++) acc[i][j] = 0.f;

    const int nkb = K >> 3;
    for (int kb = 0; kb < nkb; kb++) {
        const int cur = kb & 1;
        if (kb + 1 < nkb) {
            a4 = *(const float4*)(Ag + (kb + 1) * 8);
            b4 = *(const float4*)(Bg + (size_t)(kb + 1) * 8 * N);
        }
#pragma unroll
        for (int kk = 0; kk < 8; kk++) {
            float ar[8], br[8];
            *(float4*)&ar[0] = *(const float4*)&As[cur][kk][ty * 8];
            *(float4*)&ar[4] = *(const float4*)&As[cur][kk][ty * 8 + 4];
            *(float4*)&br[0] = *(const float4*)&Bs[cur][kk][tx * 8];
            *(float4*)&br[4] = *(const float4*)&Bs[cur][kk][tx * 8 + 4];
#pragma unroll
            for (int i = 0; i < 8; i++)
#pragma unroll
                for (int j = 0; j < 8; j++)
                    acc[i][j] = fmaf(ar[i], br[j], acc[i][j]);
        }
        if (kb + 1 < nkb) {
            const int nxt = cur ^ 1;
            As[nxt][ak + 0][am] = a4.x;
            As[nxt][ak + 1][am] = a4.y;
            As[nxt][ak + 2][am] = a4.z;
            As[nxt][ak + 3][am] = a4.w;
            *(float4*)&Bs[nxt][bk][bnn] = b4;
        }
        __syncthreads();
    }

    // epilogue
    const int row0 = bm * 128 + ty * 8;
    const int col0 = bn * 128 + tx * 8;
    float bb[8];
    if (EPI == 1 || EPI == 2) {
#pragma unroll
        for (int j = 0; j < 8; j++) bb[j] = bias[col0 + j];
    }
#pragma unroll
    for (int i = 0; i < 8; i++) {
        float* cp = C + (size_t)(row0 + i) * N + col0;
        float rv[8];
        if (EPI == 2 || EPI == 3) {
            const float* rp = res + (size_t)(row0 + i) * N + col0;
            *(float4*)&rv[0] = *(const float4*)rp;
            *(float4*)&rv[4] = *(const float4*)(rp + 4);
        }
        float ov[8];
#pragma unroll
        for (int j = 0; j < 8; j++) {
            float vv = acc[i][j];
            if (EPI == 1) vv = fmaxf(vv + bb[j], 0.f);
            if (EPI == 2) vv = vv + bb[j] + rv[j];
            if (EPI == 3) vv = vv + rv[j];
            ov[j] = vv;
        }
        *(float4*)cp       = make_float4(ov[0], ov[1], ov[2], ov[3]);
        *(float4*)(cp + 4) = make_float4(ov[4], ov[5], ov[6], ov[7]);
    }
}

// ---------------------------------------------------------------------------
// Row norms: X is [nrows, 64]; out[row] = ||X[row,:]||_2.
// 16 lanes per row (coalesced float4), shfl reduction within 16-lane group.
// ---------------------------------------------------------------------------
__global__ __launch_bounds__(256)
void rownorm64_k(const float* __restrict__ X, float* __restrict__ out, int nrows)
{
    const int t   = threadIdx.x;
    const int grp = t >> 4;
    const int ln  = t & 15;
    const int row = blockIdx.x * 16 + grp;
    if (row >= nrows) return;
    const float4 v = *(const float4*)(X + (size_t)row * 64 + ln * 4);
    float ss = v.x * v.x + v.y * v.y + v.z * v.z + v.w * v.w;
#pragma unroll
    for (int o = 8; o > 0; o >>= 1) ss += __shfl_xor_sync(0xffffffffu, ss, o);
    if (ln == 0) out[row] = sqrtf(ss);
}

// ---------------------------------------------------------------------------
// Fused cosine-similarity attention.
// Scores are bounded: |cos| <= 1, /temp=8 -> |s| <= 0.125, so exp() is safe
// without max subtraction: out = (sum_j exp(s_j) V_j) / (sum_j exp(s_j)).
// One q-row per thread; K/V streamed through smem in 64-row tiles.
// Q,K,V layout: [b, s, h, 64] flattened (= [16384, 512] row-major GEMM out).
// ---------------------------------------------------------------------------
__global__ __launch_bounds__(128)
void attn_k(const float* __restrict__ Q, const float* __restrict__ Km,
            const float* __restrict__ V, const float* __restrict__ NQ,
            const float* __restrict__ NK, float* __restrict__ O)
{
    __shared__ float Ks[64][64];
    __shared__ float Vs[64][64];
    __shared__ float nks[64];

    const int tid = threadIdx.x;
    const int b = blockIdx.z;
    const int h = blockIdx.y;
    const int r = blockIdx.x * 128 + tid;          // q row in sequence

    const size_t qoff = ((size_t)(b * SS + r) * HH + h) * 64;
    float4 qv[16];
#pragma unroll
    for (int i = 0; i < 16; i++) qv[i] = *(const float4*)(Q + qoff + i * 4);
    const float mynq = NQ[(size_t)(b * SS + r) * HH + h];

    float acc[64];
#pragma unroll
    for (int i = 0; i < 64; i++) acc[i] = 0.f;
    float lsum = 0.f;

    const int j2   = tid >> 1;     // 0..63: K/V row this thread loads
    const int part = tid & 1;      // half of the 64-float row

    for (int kt = 0; kt < SS / 64; kt++) {
        __syncthreads();
        const size_t kbase =
            ((size_t)(b * SS + kt * 64 + j2) * HH + h) * 64 + part * 32;
#pragma unroll
        for (int i = 0; i < 8; i++) {
            *(float4*)&Ks[j2][part * 32 + i * 4] = *(const float4*)(Km + kbase + i * 4);
            *(float4*)&Vs[j2][part * 32 + i * 4] = *(const float4*)(V  + kbase + i * 4);
        }
        if (tid < 64)
            nks[tid] = NK[(size_t)(b * SS + kt * 64 + tid) * HH + h];
        __syncthreads();

#pragma unroll 2
        for (int j = 0; j < 64; j++) {
            float s = 0.f;
#pragma unroll
            for (int i = 0; i < 16; i++) {
                const float4 kv = *(const float4*)&Ks[j][i * 4];
                s = fmaf(qv[i].x, kv.x, s);
                s = fmaf(qv[i].y, kv.y, s);
                s = fmaf(qv[i].z, kv.z, s);
                s = fmaf(qv[i].w, kv.w, s);
            }
            const float denom = fmaxf(mynq * nks[j], 1e-8f) * 8.0f; // temp = sqrt(64)
            const float p = expf(s / denom);
            lsum += p;
#pragma unroll
            for (int i = 0; i < 16; i++) {
                const float4 vv = *(const float4*)&Vs[j][i * 4];
                acc[i * 4 + 0] = fmaf(p, vv.x, acc[i * 4 + 0]);
                acc[i * 4 + 1] = fmaf(p, vv.y, acc[i * 4 + 1]);
                acc[i * 4 + 2] = fmaf(p, vv.z, acc[i * 4 + 2]);
                acc[i * 4 + 3] = fmaf(p, vv.w, acc[i * 4 + 3]);
            }
        }
    }

    const float inv = 1.f / lsum;
#pragma unroll
    for (int i = 0; i < 16; i++) {
        float4 o4;
        o4.x = acc[i * 4 + 0] * inv;
        o4.y = acc[i * 4 + 1] * inv;
        o4.z = acc[i * 4 + 2] * inv;
        o4.w = acc[i * 4 + 3] * inv;
        *(float4*)(O + qoff + i * 4) = o4;
    }
}

// ---------------------------------------------------------------------------
// LayerNorm over last dim (512). One block per row, 128 threads x float4.
// ---------------------------------------------------------------------------
__global__ __launch_bounds__(128)
void ln_k(const float* __restrict__ X, const float* __restrict__ gamma,
          const float* __restrict__ beta, float* __restrict__ out)
{
    __shared__ float s_sum[4], s_ss[4];
    const int tid = threadIdx.x;
    const size_t row = blockIdx.x;

    const float4 v = *(const float4*)(X + row * 512 + tid * 4);
    float sum = v.x + v.y + v.z + v.w;
    float ss  = v.x * v.x + v.y * v.y + v.z * v.z + v.w * v.w;
#pragma unroll
    for (int o = 16; o > 0; o >>= 1) {
        sum += __shfl_xor_sync(0xffffffffu, sum, o);
        ss  += __shfl_xor_sync(0xffffffffu, ss,  o);
    }
    if ((tid & 31) == 0) { s_sum[tid >> 5] = sum; s_ss[tid >> 5] = ss; }
    __syncthreads();
    sum = s_sum[0] + s_sum[1] + s_sum[2] + s_sum[3];
    ss  = s_ss[0]  + s_ss[1]  + s_ss[2]  + s_ss[3];

    const float mean = sum * (1.f / 512.f);
    const float var  = ss * (1.f / 512.f) - mean * mean;
    const float rstd = rsqrtf(var + 1e-5f);

    const int c = tid * 4;
    const float4 gv = *(const float4*)(gamma + c);
    const float4 bv = *(const float4*)(beta + c);
    float4 o4;
    o4.x = (v.x - mean) * rstd * gv.x + bv.x;
    o4.y = (v.y - mean) * rstd * gv.y + bv.y;
    o4.z = (v.z - mean) * rstd * gv.z + bv.z;
    o4.w = (v.w - mean) * rstd * gv.w + bv.w;
    *(float4*)(out + row * 512 + c) = o4;
}

// ---------------------------------------------------------------------------
// Launch sequence
// ---------------------------------------------------------------------------
extern "C" void kernel_launch(void* const* d_in, const int* in_sizes, int n_in,
                              void* d_out, int out_size)
{
    const float* x     = (const float*)d_in[0];
    const float* w_q   = (const float*)d_in[1];
    const float* w_k   = (const float*)d_in[2];
    const float* w_v   = (const float*)d_in[3];
    const float* w_o   = (const float*)d_in[4];
    const float* w_ff1 = (const float*)d_in[5];
    const float* b_ff1 = (const float*)d_in[6];
    const float* w_ff2 = (const float*)d_in[7];
    const float* b_ff2 = (const float*)d_in[8];
    const float* g1    = (const float*)d_in[9];
    const float* b1    = (const float*)d_in[10];
    const float* g2    = (const float*)d_in[11];
    const float* b2    = (const float*)d_in[12];
    float* out = (float*)d_out;

    float *q, *k, *v, *nq, *nk, *att, *t1, *h1, *ff, *t2;
    cudaGetSymbolAddress((void**)&q,   g_q);
    cudaGetSymbolAddress((void**)&k,   g_k);
    cudaGetSymbolAddress((void**)&v,   g_v);
    cudaGetSymbolAddress((void**)&nq,  g_nq);
    cudaGetSymbolAddress((void**)&nk,  g_nk);
    cudaGetSymbolAddress((void**)&att, g_att);
    cudaGetSymbolAddress((void**)&t1,  g_t1);
    cudaGetSymbolAddress((void**)&h1,  g_h1);
    cudaGetSymbolAddress((void**)&ff,  g_ff);
    cudaGetSymbolAddress((void**)&t2,  g_t2);

    const dim3 g512(512 / 128, MM / 128);    // (4, 128)
    const dim3 gff1(DFFN / 128, MM / 128);   // (16, 128)

    // Q/K/V projections ([16384,512] row-major == [b,s,h,dk])
    sgemm_k<0><<<g512, 256>>>(x, w_q, q, MM, 512, 512, nullptr, nullptr);
    sgemm_k<0><<<g512, 256>>>(x, w_k, k, MM, 512, 512, nullptr, nullptr);
    sgemm_k<0><<<g512, 256>>>(x, w_v, v, MM, 512, 512, nullptr, nullptr);

    // per-(b,s,h) L2 norms of q and k
    rownorm64_k<<<(MM * HH) / 16, 256>>>(q, nq, MM * HH);
    rownorm64_k<<<(MM * HH) / 16, 256>>>(k, nk, MM * HH);

    // fused cosine attention
    attn_k<<<dim3(SS / 128, HH, BB), 128>>>(q, k, v, nq, nk, att);

    // O-projection + residual x
    sgemm_k<3><<<g512, 256>>>(att, w_o, t1, MM, 512, 512, nullptr, x);

    // LN1
    ln_k<<<MM, 128>>>(t1, g1, b1, h1);

    // FFN1 + bias + relu
    sgemm_k<1><<<gff1, 256>>>(h1, w_ff1, ff, MM, DFFN, 512, b_ff1, nullptr);

    // FFN2 + bias + residual h1
    sgemm_k<2><<<g512, 256>>>(ff, w_ff2, t2, MM, 512, DFFN, b_ff2, h1);

    // LN2 -> output
    ln_k<<<MM, 128>>>(t2, g2, b2, out);
}

// round 6
// speedup vs baseline: 1.4857x; 1.4857x over previous
#include <cuda_runtime.h>
#include <cuda_bf16.h>
#include <cstdint>

// Problem constants
#define BB   32
#define SS   512
#define DDIM 512
#define HH   8
#define MM   (BB * SS)     // 16384 tokens
#define DFFN 2048

// ===========================================================================
// PTX helpers (baseline ISA only — no sm_103a-variant instructions; the
// harness builds for compute_103, which rejects tcgen05/TMEM)
// ===========================================================================
__device__ __forceinline__ uint32_t smem_to_u32(const void* p) {
    uint32_t a;
    asm("{ .reg .u64 t; cvta.to.shared.u64 t, %1; cvt.u32.u64 %0, t; }"
        : "=r"(a) : "l"(p));
    return a;
}

#define CP_ASYNC16(smem, gptr) \
    asm volatile("cp.async.cg.shared.global [%0], [%1], 16;" \
        :: "r"(smem), "l"(gptr) : "memory")
#define CP_COMMIT() asm volatile("cp.async.commit_group;" ::: "memory")

#define LDSM_X4(r0, r1, r2, r3, addr) \
    asm volatile("ldmatrix.sync.aligned.m8n8.x4.shared.b16 {%0,%1,%2,%3}, [%4];" \
        : "=r"(r0), "=r"(r1), "=r"(r2), "=r"(r3) : "r"(addr))

#define MMA16816(d, a0, a1, a2, a3, b0, b1) \
    asm volatile("mma.sync.aligned.m16n8k16.row.col.f32.bf16.bf16.f32 " \
        "{%0,%1,%2,%3}, {%4,%5,%6,%7}, {%8,%9}, {%0,%1,%2,%3};" \
        : "+f"((d)[0]), "+f"((d)[1]), "+f"((d)[2]), "+f"((d)[3]) \
        : "r"(a0), "r"(a1), "r"(a2), "r"(a3), "r"(b0), "r"(b1))

// ===========================================================================
// Scratch (device globals)
// ===========================================================================
__device__ __nv_bfloat16 g_xh [MM * DDIM], g_xl [MM * DDIM];
__device__ __nv_bfloat16 g_wqh[DDIM * DDIM], g_wql[DDIM * DDIM];
__device__ __nv_bfloat16 g_wkh[DDIM * DDIM], g_wkl[DDIM * DDIM];
__device__ __nv_bfloat16 g_wvh[DDIM * DDIM], g_wvl[DDIM * DDIM];
__device__ __nv_bfloat16 g_woh[DDIM * DDIM], g_wol[DDIM * DDIM];
__device__ __nv_bfloat16 g_w1h[DFFN * DDIM], g_w1l[DFFN * DDIM];
__device__ __nv_bfloat16 g_w2h[DDIM * DFFN], g_w2l[DDIM * DFFN];
__device__ __nv_bfloat16 g_ath[MM * DDIM], g_atl[MM * DDIM];
__device__ __nv_bfloat16 g_h1h[MM * DDIM], g_h1l[MM * DDIM];
__device__ __nv_bfloat16 g_ffh[(size_t)MM * DFFN], g_ffl[(size_t)MM * DFFN];
__device__ float g_q [MM * DDIM], g_k [MM * DDIM], g_v [MM * DDIM];
__device__ float g_rq[MM * HH],   g_rk[MM * HH];
__device__ float g_t1[MM * DDIM], g_h1[MM * DDIM], g_t2[MM * DDIM];

__device__ __forceinline__ void bsplit(float x, __nv_bfloat16& hi, __nv_bfloat16& lo) {
    hi = __float2bfloat16(x);
    lo = __float2bfloat16(x - __bfloat162float(hi));
}

// ===========================================================================
// fp32 -> bf16 hi/lo split (elementwise)
// ===========================================================================
__global__ __launch_bounds__(256)
void split_k(const float4* __restrict__ X, __nv_bfloat162* __restrict__ Hi,
             __nv_bfloat162* __restrict__ Lo, int n4)
{
    int i = blockIdx.x * 256 + threadIdx.x;
    if (i >= n4) return;
    float4 v = X[i];
    __nv_bfloat16 h0, h1, h2, h3, l0, l1, l2, l3;
    bsplit(v.x, h0, l0); bsplit(v.y, h1, l1);
    bsplit(v.z, h2, l2); bsplit(v.w, h3, l3);
    Hi[i * 2]     = __halves2bfloat162(h0, h1);
    Hi[i * 2 + 1] = __halves2bfloat162(h2, h3);
    Lo[i * 2]     = __halves2bfloat162(l0, l1);
    Lo[i * 2 + 1] = __halves2bfloat162(l2, l3);
}

// ===========================================================================
// Weight transpose + split: W[K,N] fp32 -> Thi/Tlo [N,K] bf16 (K-major)
// ===========================================================================
__global__ __launch_bounds__(256)
void tsplit_k(const float* __restrict__ W, __nv_bfloat16* __restrict__ Thi,
              __nv_bfloat16* __restrict__ Tlo, int K, int N)
{
    __shared__ float t[32][33];
    const int tx = threadIdx.x & 31, ty = threadIdx.x >> 5;
    const int n0 = blockIdx.x * 32, k0 = blockIdx.y * 32;
#pragma unroll
    for (int j = 0; j < 4; j++)
        t[ty + j * 8][tx] = W[(size_t)(k0 + ty + j * 8) * N + n0 + tx];
    __syncthreads();
#pragma unroll
    for (int j = 0; j < 4; j++) {
        const float v = t[tx][ty + j * 8];
        __nv_bfloat16 hi, lo;
        bsplit(v, hi, lo);
        const size_t o = (size_t)(n0 + ty + j * 8) * K + k0 + tx;
        Thi[o] = hi; Tlo[o] = lo;
    }
}

// ===========================================================================
// bf16-split HMMA GEMM: C[M,N] = (Ahi+Alo)[M,K] @ (Bhi+Blo)[N,K]^T
// 3-term split (hi*hi + hi*lo + lo*hi), fp32 accumulators.
// mma.sync.m16n8k16 bf16 (tensor pipe), ldmatrix, cp.async double buffering.
// BM=BN=128, BK=32, 256 threads (8 warps, 2x4 grid, warp tile m64n32).
//   EPI 0: C = acc
//   EPI 1: Chi/Clo = split(relu(acc + bias))     (bf16 out only)
//   EPI 2: C = acc + bias + res
//   EPI 3: C = acc + res
// ===========================================================================
#define SROW 40   // bf16 elems per smem row (80 B stride: 16B-aligned, ldmatrix conflict-free)

template <int EPI>
__global__ __launch_bounds__(256, 2)
void mgemm_k(const __nv_bfloat16* __restrict__ Ahi, const __nv_bfloat16* __restrict__ Alo,
             const __nv_bfloat16* __restrict__ Bhi, const __nv_bfloat16* __restrict__ Blo,
             float* __restrict__ C, int M, int N, int K,
             const float* __restrict__ bias, const float* __restrict__ res,
             __nv_bfloat16* __restrict__ Chi, __nv_bfloat16* __restrict__ Clo)
{
    __shared__ __nv_bfloat16 As[2][128 * SROW];
    __shared__ __nv_bfloat16 Bs[2][128 * SROW];

    const int tid  = threadIdx.x;
    const int wid  = tid >> 5, lane = tid & 31;
    const int wr   = wid >> 2, wc = wid & 3;      // warp grid 2 x 4
    const int bm   = blockIdx.y, bn = blockIdx.x;

    // cp.async mapping: 512 16B-chunks per tile; thread covers chunks 2t, 2t+1
    const int lrow = tid >> 1;            // 0..127
    const int lkc0 = (tid & 1) * 2;       // chunk col 0 or 2 (of 4 per row)

    const __nv_bfloat16* Asel[3] = {Ahi, Ahi, Alo};
    const __nv_bfloat16* Bsel[3] = {Bhi, Blo, Bhi};
    const size_t aoff = (size_t)(bm * 128 + lrow) * K + lkc0 * 8;
    const size_t boff = (size_t)(bn * 128 + lrow) * K + lkc0 * 8;

    const uint32_t sAd[2] = { smem_to_u32(&As[0][lrow * SROW + lkc0 * 8]),
                              smem_to_u32(&As[1][lrow * SROW + lkc0 * 8]) };
    const uint32_t sBd[2] = { smem_to_u32(&Bs[0][lrow * SROW + lkc0 * 8]),
                              smem_to_u32(&Bs[1][lrow * SROW + lkc0 * 8]) };

    auto issue = [&](int t, int kb, int buf) {
        const __nv_bfloat16* ga = Asel[t] + aoff + kb * 32;
        const __nv_bfloat16* gb = Bsel[t] + boff + kb * 32;
        CP_ASYNC16(sAd[buf],      ga);
        CP_ASYNC16(sAd[buf] + 16, ga + 8);
        CP_ASYNC16(sBd[buf],      gb);
        CP_ASYNC16(sBd[buf] + 16, gb + 8);
        CP_COMMIT();
    };

    float acc[4][4][4];
#pragma unroll
    for (int i = 0; i < 4; i++)
#pragma unroll
        for (int j = 0; j < 4; j++)
#pragma unroll
            for (int l = 0; l < 4; l++) acc[i][j][l] = 0.f;

    // ldmatrix per-lane address components
    const int q4     = lane >> 3;
    const int arow_l = (q4 & 1) * 8 + (lane & 7);
    const int akc_l  = (q4 >> 1) * 8;
    const int brow_l = (q4 >> 1) * 8 + (lane & 7);
    const int bkc_l  = (q4 & 1) * 8;

    auto compute = [&](int buf) {
        const uint32_t abase = smem_to_u32(&As[buf][0]);
        const uint32_t bbase = smem_to_u32(&Bs[buf][0]);
#pragma unroll
        for (int ks = 0; ks < 2; ks++) {
            uint32_t a[4][4], b[2][4];
#pragma unroll
            for (int mi = 0; mi < 4; mi++) {
                const uint32_t ad = abase +
                    ((wr * 64 + mi * 16 + arow_l) * SROW + ks * 16 + akc_l) * 2;
                LDSM_X4(a[mi][0], a[mi][1], a[mi][2], a[mi][3], ad);
            }
#pragma unroll
            for (int nb = 0; nb < 2; nb++) {
                const uint32_t bd = bbase +
                    ((wc * 32 + nb * 16 + brow_l) * SROW + ks * 16 + bkc_l) * 2;
                LDSM_X4(b[nb][0], b[nb][1], b[nb][2], b[nb][3], bd);
            }
#pragma unroll
            for (int mi = 0; mi < 4; mi++)
#pragma unroll
                for (int nb = 0; nb < 2; nb++) {
                    MMA16816(acc[mi][nb * 2 + 0],
                             a[mi][0], a[mi][1], a[mi][2], a[mi][3],
                             b[nb][0], b[nb][1]);
                    MMA16816(acc[mi][nb * 2 + 1],
                             a[mi][0], a[mi][1], a[mi][2], a[mi][3],
                             b[nb][2], b[nb][3]);
                }
        }
    };

    const int nkb = K >> 5;
    const int NIT = 3 * nkb;

    int ti = 0, ki = 0;
    issue(0, 0, 0);
    if (++ki == nkb) { ki = 0; ++ti; }

    for (int it = 0; it < NIT; ++it) {
        if (it + 1 < NIT) {
            issue(ti, ki, (it + 1) & 1);
            if (++ki == nkb) { ki = 0; ++ti; }
            asm volatile("cp.async.wait_group 1;" ::: "memory");
        } else {
            asm volatile("cp.async.wait_group 0;" ::: "memory");
        }
        __syncthreads();
        compute(it & 1);
        __syncthreads();
    }

    // ---- epilogue ----
    const int r4 = lane >> 2;
    const int c2 = (lane & 3) * 2;
#pragma unroll
    for (int mi = 0; mi < 4; mi++) {
#pragma unroll
        for (int half = 0; half < 2; half++) {
            const int row = bm * 128 + wr * 64 + mi * 16 + r4 + half * 8;
#pragma unroll
            for (int ni = 0; ni < 4; ni++) {
                const int col = bn * 128 + wc * 32 + ni * 8 + c2;
                float v0 = acc[mi][ni][half * 2 + 0];
                float v1 = acc[mi][ni][half * 2 + 1];
                if (EPI == 1) {
                    v0 = fmaxf(v0 + bias[col],     0.f);
                    v1 = fmaxf(v1 + bias[col + 1], 0.f);
                    __nv_bfloat16 h0, h1, l0, l1;
                    bsplit(v0, h0, l0); bsplit(v1, h1, l1);
                    *(__nv_bfloat162*)(Chi + (size_t)row * N + col) = __halves2bfloat162(h0, h1);
                    *(__nv_bfloat162*)(Clo + (size_t)row * N + col) = __halves2bfloat162(l0, l1);
                } else {
                    if (EPI == 2) { v0 += bias[col]; v1 += bias[col + 1]; }
                    if (EPI == 2 || EPI == 3) {
                        const float2 rv = *(const float2*)(res + (size_t)row * N + col);
                        v0 += rv.x; v1 += rv.y;
                    }
                    *(float2*)(C + (size_t)row * N + col) = make_float2(v0, v1);
                }
            }
        }
    }
}

// ===========================================================================
// Row reciprocal norms: X is [nrows, 64]; out[row] = scale / ||X[row,:]||.
// ===========================================================================
__global__ __launch_bounds__(256)
void rownorm64_k(const float* __restrict__ X, float* __restrict__ out,
                 int nrows, float scale)
{
    const int t   = threadIdx.x;
    const int grp = t >> 4;
    const int ln  = t & 15;
    const int row = blockIdx.x * 16 + grp;
    if (row >= nrows) return;
    const float4 v = *(const float4*)(X + (size_t)row * 64 + ln * 4);
    float ss = v.x * v.x + v.y * v.y + v.z * v.z + v.w * v.w;
#pragma unroll
    for (int o = 8; o > 0; o >>= 1) ss += __shfl_xor_sync(0xffffffffu, ss, o);
    if (ln == 0) out[row] = scale * rsqrtf(fmaxf(ss, 1e-24f));
}

// ===========================================================================
// Fused cosine-similarity attention.
// x = dot(q,k) / (8*|q||k|) with |x| <= 0.125 exactly, so exp(x) is evaluated
// by a degree-5 Taylor polynomial (rel err ~6e-9) — zero MUFU in the hot loop.
// RQ = 0.125/|q| pre-folded into the q registers; RK = 1/|k| per key.
// Output written directly as bf16 hi/lo split (feeds O-projection GEMM).
// ===========================================================================
__global__ __launch_bounds__(128)
void attn_k(const float* __restrict__ Q, const float* __restrict__ Km,
            const float* __restrict__ V, const float* __restrict__ RQ,
            const float* __restrict__ RK,
            __nv_bfloat16* __restrict__ Ohi, __nv_bfloat16* __restrict__ Olo)
{
    __shared__ float Ks[64][64];
    __shared__ float Vs[64][64];
    __shared__ float rks[64];

    const int tid = threadIdx.x;
    const int b = blockIdx.z;
    const int h = blockIdx.y;
    const int r = blockIdx.x * 128 + tid;

    const size_t qoff = ((size_t)(b * SS + r) * HH + h) * 64;
    const float myrq = RQ[(size_t)(b * SS + r) * HH + h];   // 0.125/|q|
    float4 qv[16];
#pragma unroll
    for (int i = 0; i < 16; i++) {
        qv[i] = *(const float4*)(Q + qoff + i * 4);
        qv[i].x *= myrq; qv[i].y *= myrq; qv[i].z *= myrq; qv[i].w *= myrq;
    }

    float acc[64];
#pragma unroll
    for (int i = 0; i < 64; i++) acc[i] = 0.f;
    float lsum = 0.f;

    const int j2   = tid >> 1;
    const int part = tid & 1;

    for (int kt = 0; kt < SS / 64; kt++) {
        __syncthreads();
        const size_t kbase =
            ((size_t)(b * SS + kt * 64 + j2) * HH + h) * 64 + part * 32;
#pragma unroll
        for (int i = 0; i < 8; i++) {
            *(float4*)&Ks[j2][part * 32 + i * 4] = *(const float4*)(Km + kbase + i * 4);
            *(float4*)&Vs[j2][part * 32 + i * 4] = *(const float4*)(V  + kbase + i * 4);
        }
        if (tid < 64)
            rks[tid] = RK[(size_t)(b * SS + kt * 64 + tid) * HH + h];
        __syncthreads();

#pragma unroll 2
        for (int j = 0; j < 64; j++) {
            float s = 0.f;
#pragma unroll
            for (int i = 0; i < 16; i++) {
                const float4 kv = *(const float4*)&Ks[j][i * 4];
                s = fmaf(qv[i].x, kv.x, s);
                s = fmaf(qv[i].y, kv.y, s);
                s = fmaf(qv[i].z, kv.z, s);
                s = fmaf(qv[i].w, kv.w, s);
            }
            const float x = s * rks[j];           // |x| <= 0.125
            float p = fmaf(8.3333333e-3f, x, 4.1666667e-2f);
            p = fmaf(p, x, 0.16666667f);
            p = fmaf(p, x, 0.5f);
            p = fmaf(p, x, 1.0f);
            p = fmaf(p, x, 1.0f);                 // exp(x), rel err ~6e-9
            lsum += p;
#pragma unroll
            for (int i = 0; i < 16; i++) {
                const float4 vv = *(const float4*)&Vs[j][i * 4];
                acc[i * 4 + 0] = fmaf(p, vv.x, acc[i * 4 + 0]);
                acc[i * 4 + 1] = fmaf(p, vv.y, acc[i * 4 + 1]);
                acc[i * 4 + 2] = fmaf(p, vv.z, acc[i * 4 + 2]);
                acc[i * 4 + 3] = fmaf(p, vv.w, acc[i * 4 + 3]);
            }
        }
    }

    const float inv = 1.f / lsum;
    __nv_bfloat162* Oh2 = (__nv_bfloat162*)Ohi;
    __nv_bfloat162* Ol2 = (__nv_bfloat162*)Olo;
    const size_t o2 = qoff >> 1;
#pragma unroll
    for (int i = 0; i < 16; i++) {
        const float o0 = acc[i * 4 + 0] * inv;
        const float o1 = acc[i * 4 + 1] * inv;
        const float o2v = acc[i * 4 + 2] * inv;
        const float o3 = acc[i * 4 + 3] * inv;
        __nv_bfloat16 h0, h1, h2, h3, l0, l1, l2, l3;
        bsplit(o0, h0, l0); bsplit(o1, h1, l1);
        bsplit(o2v, h2, l2); bsplit(o3, h3, l3);
        Oh2[o2 + i * 2]     = __halves2bfloat162(h0, h1);
        Oh2[o2 + i * 2 + 1] = __halves2bfloat162(h2, h3);
        Ol2[o2 + i * 2]     = __halves2bfloat162(l0, l1);
        Ol2[o2 + i * 2 + 1] = __halves2bfloat162(l2, l3);
    }
}

// ===========================================================================
// LayerNorm over last dim (512), optional fused bf16 hi/lo split output.
// ===========================================================================
__global__ __launch_bounds__(128)
void ln_k(const float* __restrict__ X, const float* __restrict__ gamma,
          const float* __restrict__ beta, float* __restrict__ out,
          __nv_bfloat16* __restrict__ hi, __nv_bfloat16* __restrict__ lo)
{
    __shared__ float s_sum[4], s_ss[4];
    const int tid = threadIdx.x;
    const size_t row = blockIdx.x;

    const float4 v = *(const float4*)(X + row * 512 + tid * 4);
    float sum = v.x + v.y + v.z + v.w;
    float ss  = v.x * v.x + v.y * v.y + v.z * v.z + v.w * v.w;
#pragma unroll
    for (int o = 16; o > 0; o >>= 1) {
        sum += __shfl_xor_sync(0xffffffffu, sum, o);
        ss  += __shfl_xor_sync(0xffffffffu, ss,  o);
    }
    if ((tid & 31) == 0) { s_sum[tid >> 5] = sum; s_ss[tid >> 5] = ss; }
    __syncthreads();
    sum = s_sum[0] + s_sum[1] + s_sum[2] + s_sum[3];
    ss  = s_ss[0]  + s_ss[1]  + s_ss[2]  + s_ss[3];

    const float mean = sum * (1.f / 512.f);
    const float var  = ss * (1.f / 512.f) - mean * mean;
    const float rstd = rsqrtf(var + 1e-5f);

    const int c = tid * 4;
    const float4 gv = *(const float4*)(gamma + c);
    const float4 bv = *(const float4*)(beta + c);
    float4 o4;
    o4.x = (v.x - mean) * rstd * gv.x + bv.x;
    o4.y = (v.y - mean) * rstd * gv.y + bv.y;
    o4.z = (v.z - mean) * rstd * gv.z + bv.z;
    o4.w = (v.w - mean) * rstd * gv.w + bv.w;
    *(float4*)(out + row * 512 + c) = o4;

    if (hi != nullptr) {
        __nv_bfloat16 h0, h1, h2, h3, l0, l1, l2, l3;
        bsplit(o4.x, h0, l0); bsplit(o4.y, h1, l1);
        bsplit(o4.z, h2, l2); bsplit(o4.w, h3, l3);
        const size_t i2 = row * 256 + tid * 2;
        ((__nv_bfloat162*)hi)[i2]     = __halves2bfloat162(h0, h1);
        ((__nv_bfloat162*)hi)[i2 + 1] = __halves2bfloat162(h2, h3);
        ((__nv_bfloat162*)lo)[i2]     = __halves2bfloat162(l0, l1);
        ((__nv_bfloat162*)lo)[i2 + 1] = __halves2bfloat162(l2, l3);
    }
}

// ===========================================================================
// Launch sequence
// ===========================================================================
extern "C" void kernel_launch(void* const* d_in, const int* in_sizes, int n_in,
                              void* d_out, int out_size)
{
    const float* x     = (const float*)d_in[0];
    const float* w_q   = (const float*)d_in[1];
    const float* w_k   = (const float*)d_in[2];
    const float* w_v   = (const float*)d_in[3];
    const float* w_o   = (const float*)d_in[4];
    const float* w_ff1 = (const float*)d_in[5];
    const float* b_ff1 = (const float*)d_in[6];
    const float* w_ff2 = (const float*)d_in[7];
    const float* b_ff2 = (const float*)d_in[8];
    const float* g1    = (const float*)d_in[9];
    const float* b1    = (const float*)d_in[10];
    const float* g2    = (const float*)d_in[11];
    const float* b2    = (const float*)d_in[12];
    float* out = (float*)d_out;

    __nv_bfloat16 *xh, *xl, *wqh, *wql, *wkh, *wkl, *wvh, *wvl, *woh, *wol;
    __nv_bfloat16 *w1h, *w1l, *w2h, *w2l, *ath, *atl, *h1h, *h1l, *ffh, *ffl;
    float *q, *k, *v, *rq, *rk, *t1, *h1, *t2;
    cudaGetSymbolAddress((void**)&xh,  g_xh);  cudaGetSymbolAddress((void**)&xl,  g_xl);
    cudaGetSymbolAddress((void**)&wqh, g_wqh); cudaGetSymbolAddress((void**)&wql, g_wql);
    cudaGetSymbolAddress((void**)&wkh, g_wkh); cudaGetSymbolAddress((void**)&wkl, g_wkl);
    cudaGetSymbolAddress((void**)&wvh, g_wvh); cudaGetSymbolAddress((void**)&wvl, g_wvl);
    cudaGetSymbolAddress((void**)&woh, g_woh); cudaGetSymbolAddress((void**)&wol, g_wol);
    cudaGetSymbolAddress((void**)&w1h, g_w1h); cudaGetSymbolAddress((void**)&w1l, g_w1l);
    cudaGetSymbolAddress((void**)&w2h, g_w2h); cudaGetSymbolAddress((void**)&w2l, g_w2l);
    cudaGetSymbolAddress((void**)&ath, g_ath); cudaGetSymbolAddress((void**)&atl, g_atl);
    cudaGetSymbolAddress((void**)&h1h, g_h1h); cudaGetSymbolAddress((void**)&h1l, g_h1l);
    cudaGetSymbolAddress((void**)&ffh, g_ffh); cudaGetSymbolAddress((void**)&ffl, g_ffl);
    cudaGetSymbolAddress((void**)&q,  g_q);  cudaGetSymbolAddress((void**)&k,  g_k);
    cudaGetSymbolAddress((void**)&v,  g_v);  cudaGetSymbolAddress((void**)&rq, g_rq);
    cudaGetSymbolAddress((void**)&rk, g_rk); cudaGetSymbolAddress((void**)&t1, g_t1);
    cudaGetSymbolAddress((void**)&h1, g_h1); cudaGetSymbolAddress((void**)&t2, g_t2);

    // --- input + weight prep ---
    const int n4 = MM * DDIM / 4;
    split_k<<<n4 / 256, 256>>>((const float4*)x, (__nv_bfloat162*)xh,
                               (__nv_bfloat162*)xl, n4);
    tsplit_k<<<dim3(DDIM / 32, DDIM / 32), 256>>>(w_q,   wqh, wql, DDIM, DDIM);
    tsplit_k<<<dim3(DDIM / 32, DDIM / 32), 256>>>(w_k,   wkh, wkl, DDIM, DDIM);
    tsplit_k<<<dim3(DDIM / 32, DDIM / 32), 256>>>(w_v,   wvh, wvl, DDIM, DDIM);
    tsplit_k<<<dim3(DDIM / 32, DDIM / 32), 256>>>(w_o,   woh, wol, DDIM, DDIM);
    tsplit_k<<<dim3(DFFN / 32, DDIM / 32), 256>>>(w_ff1, w1h, w1l, DDIM, DFFN);
    tsplit_k<<<dim3(DDIM / 32, DFFN / 32), 256>>>(w_ff2, w2h, w2l, DFFN, DDIM);

    const dim3 g512(DDIM / 128, MM / 128);   // (4, 128)
    const dim3 gff1(DFFN / 128, MM / 128);   // (16, 128)

    // --- Q/K/V projections (fp32 out, [16384,512] == [b,s,h,dk]) ---
    mgemm_k<0><<<g512, 256>>>(xh, xl, wqh, wql, q, MM, DDIM, DDIM,
                              nullptr, nullptr, nullptr, nullptr);
    mgemm_k<0><<<g512, 256>>>(xh, xl, wkh, wkl, k, MM, DDIM, DDIM,
                              nullptr, nullptr, nullptr, nullptr);
    mgemm_k<0><<<g512, 256>>>(xh, xl, wvh, wvl, v, MM, DDIM, DDIM,
                              nullptr, nullptr, nullptr, nullptr);

    // --- per-(b,s,h) reciprocal norms (q pre-folds the 1/temp=1/8) ---
    rownorm64_k<<<(MM * HH) / 16, 256>>>(q, rq, MM * HH, 0.125f);
    rownorm64_k<<<(MM * HH) / 16, 256>>>(k, rk, MM * HH, 1.0f);

    // --- fused cosine attention -> bf16 split output ---
    attn_k<<<dim3(SS / 128, HH, BB), 128>>>(q, k, v, rq, rk, ath, atl);

    // --- O-projection + residual x -> t1 ---
    mgemm_k<3><<<g512, 256>>>(ath, atl, woh, wol, t1, MM, DDIM, DDIM,
                              nullptr, x, nullptr, nullptr);

    // --- LN1 -> h1 (fp32) + bf16 split ---
    ln_k<<<MM, 128>>>(t1, g1, b1, h1, h1h, h1l);

    // --- FFN1 + bias + relu -> bf16 split only ---
    mgemm_k<1><<<gff1, 256>>>(h1h, h1l, w1h, w1l, nullptr, MM, DFFN, DDIM,
                              b_ff1, nullptr, ffh, ffl);

    // --- FFN2 + bias + residual h1 -> t2 ---
    mgemm_k<2><<<g512, 256>>>(ffh, ffl, w2h, w2l, t2, MM, DDIM, DFFN,
                              b_ff2, h1, nullptr, nullptr);

    // --- LN2 -> output ---
    ln_k<<<MM, 128>>>(t2, g2, b2, out, nullptr, nullptr);
}

// round 7
// speedup vs baseline: 1.7218x; 1.1589x over previous
#include <cuda_runtime.h>
#include <cuda_bf16.h>
#include <cstdint>

// Problem constants
#define BB   32
#define SS   512
#define DDIM 512
#define HH   8
#define MM   (BB * SS)     // 16384 tokens
#define DFFN 2048

// ===========================================================================
// PTX helpers (baseline ISA only — harness compiles for compute_103, which
// rejects sm_103a-variant instructions like tcgen05/TMEM)
// ===========================================================================
__device__ __forceinline__ uint32_t smem_to_u32(const void* p) {
    uint32_t a;
    asm("{ .reg .u64 t; cvta.to.shared.u64 t, %1; cvt.u32.u64 %0, t; }"
        : "=r"(a) : "l"(p));
    return a;
}

#define CP_ASYNC16(smem, gptr) \
    asm volatile("cp.async.cg.shared.global [%0], [%1], 16;" \
        :: "r"(smem), "l"(gptr) : "memory")
#define CP_COMMIT() asm volatile("cp.async.commit_group;" ::: "memory")

#define LDSM_X4(r0, r1, r2, r3, addr) \
    asm volatile("ldmatrix.sync.aligned.m8n8.x4.shared.b16 {%0,%1,%2,%3}, [%4];" \
        : "=r"(r0), "=r"(r1), "=r"(r2), "=r"(r3) : "r"(addr))

#define MMA16816(d, a0, a1, a2, a3, b0, b1) \
    asm volatile("mma.sync.aligned.m16n8k16.row.col.f32.bf16.bf16.f32 " \
        "{%0,%1,%2,%3}, {%4,%5,%6,%7}, {%8,%9}, {%0,%1,%2,%3};" \
        : "+f"((d)[0]), "+f"((d)[1]), "+f"((d)[2]), "+f"((d)[3]) \
        : "r"(a0), "r"(a1), "r"(a2), "r"(a3), "r"(b0), "r"(b1))

// ===========================================================================
// Scratch (device globals)
// ===========================================================================
__device__ __nv_bfloat16 g_xh [MM * DDIM], g_xl [MM * DDIM];
__device__ __nv_bfloat16 g_wqh[DDIM * DDIM], g_wql[DDIM * DDIM];
__device__ __nv_bfloat16 g_wkh[DDIM * DDIM], g_wkl[DDIM * DDIM];
__device__ __nv_bfloat16 g_wvh[DDIM * DDIM], g_wvl[DDIM * DDIM];
__device__ __nv_bfloat16 g_woh[DDIM * DDIM], g_wol[DDIM * DDIM];
__device__ __nv_bfloat16 g_w1h[DFFN * DDIM], g_w1l[DFFN * DDIM];
__device__ __nv_bfloat16 g_w2h[DDIM * DFFN], g_w2l[DDIM * DFFN];
__device__ __nv_bfloat16 g_ath[MM * DDIM], g_atl[MM * DDIM];
__device__ __nv_bfloat16 g_h1h[MM * DDIM], g_h1l[MM * DDIM];
__device__ __nv_bfloat16 g_ffh[(size_t)MM * DFFN], g_ffl[(size_t)MM * DFFN];
__device__ float g_q [MM * DDIM], g_k [MM * DDIM], g_v [MM * DDIM];
__device__ float g_rq[MM * HH],   g_rk[MM * HH];
__device__ float g_t1[MM * DDIM], g_h1[MM * DDIM], g_t2[MM * DDIM];

__device__ __forceinline__ void bsplit(float x, __nv_bfloat16& hi, __nv_bfloat16& lo) {
    hi = __float2bfloat16(x);
    lo = __float2bfloat16(x - __bfloat162float(hi));
}

// ===========================================================================
// fp32 -> bf16 hi/lo split (elementwise)
// ===========================================================================
__global__ __launch_bounds__(256)
void split_k(const float4* __restrict__ X, __nv_bfloat162* __restrict__ Hi,
             __nv_bfloat162* __restrict__ Lo, int n4)
{
    int i = blockIdx.x * 256 + threadIdx.x;
    if (i >= n4) return;
    float4 v = X[i];
    __nv_bfloat16 h0, h1, h2, h3, l0, l1, l2, l3;
    bsplit(v.x, h0, l0); bsplit(v.y, h1, l1);
    bsplit(v.z, h2, l2); bsplit(v.w, h3, l3);
    Hi[i * 2]     = __halves2bfloat162(h0, h1);
    Hi[i * 2 + 1] = __halves2bfloat162(h2, h3);
    Lo[i * 2]     = __halves2bfloat162(l0, l1);
    Lo[i * 2 + 1] = __halves2bfloat162(l2, l3);
}

// ===========================================================================
// Weight transpose + split: W[K,N] fp32 -> Thi/Tlo [N,K] bf16 (K-major)
// ===========================================================================
__global__ __launch_bounds__(256)
void tsplit_k(const float* __restrict__ W, __nv_bfloat16* __restrict__ Thi,
              __nv_bfloat16* __restrict__ Tlo, int K, int N)
{
    __shared__ float t[32][33];
    const int tx = threadIdx.x & 31, ty = threadIdx.x >> 5;
    const int n0 = blockIdx.x * 32, k0 = blockIdx.y * 32;
#pragma unroll
    for (int j = 0; j < 4; j++)
        t[ty + j * 8][tx] = W[(size_t)(k0 + ty + j * 8) * N + n0 + tx];
    __syncthreads();
#pragma unroll
    for (int j = 0; j < 4; j++) {
        const float v = t[tx][ty + j * 8];
        __nv_bfloat16 hi, lo;
        bsplit(v, hi, lo);
        const size_t o = (size_t)(n0 + ty + j * 8) * K + k0 + tx;
        Thi[o] = hi; Tlo[o] = lo;
    }
}

// ===========================================================================
// bf16-split HMMA GEMM: C[M,N] = (Ahi+Alo)[M,K] @ (Bhi+Blo)[N,K]^T
// 3-term split (hi*hi + hi*lo + lo*hi), fp32 accumulators.
// All 4 tiles (Ahi,Alo,Bhi,Blo) loaded per k-block; all 3 terms computed
// between one barrier pair (96 MMAs/warp per sync). Double-buffered cp.async.
// BM=BN=128, BK=32, 256 threads (8 warps, 2x4 grid, warp tile m64n32).
//   EPI 0: C = acc
//   EPI 1: Chi/Clo = split(relu(acc + bias))     (bf16 out only)
//   EPI 2: C = acc + bias + res
//   EPI 3: C = acc + res
// ===========================================================================
#define SROW   40                    // 80 B smem row stride, ldmatrix conflict-free
#define TILE_E (128 * SROW)          // elems per tile
static constexpr int MG_SMEM = 2 * 4 * TILE_E * 2;   // 81920 B

template <int EPI>
__global__ __launch_bounds__(256, 2)
void mgemm_k(const __nv_bfloat16* __restrict__ Ahi, const __nv_bfloat16* __restrict__ Alo,
             const __nv_bfloat16* __restrict__ Bhi, const __nv_bfloat16* __restrict__ Blo,
             float* __restrict__ C, int M, int N, int K,
             const float* __restrict__ bias, const float* __restrict__ res,
             __nv_bfloat16* __restrict__ Chi, __nv_bfloat16* __restrict__ Clo)
{
    extern __shared__ __nv_bfloat16 sm[];
    const uint32_t sm0 = smem_to_u32(sm);

    const int tid  = threadIdx.x;
    const int wid  = tid >> 5, lane = tid & 31;
    const int wr   = wid >> 2, wc = wid & 3;      // warp grid 2 x 4
    const int bm   = blockIdx.y, bn = blockIdx.x;

    // cp.async mapping: each thread covers 2 x 16B per tile
    const int lrow = tid >> 1;            // 0..127
    const int lkc0 = (tid & 1) * 2;       // 16B-chunk col 0 or 2

    const size_t aoff = (size_t)(bm * 128 + lrow) * K + lkc0 * 8;
    const size_t boff = (size_t)(bn * 128 + lrow) * K + lkc0 * 8;
    const uint32_t thr_off = (uint32_t)(lrow * SROW + lkc0 * 8) * 2;

    auto issue = [&](int buf, int kb) {
        const __nv_bfloat16* ga_h = Ahi + aoff + kb * 32;
        const __nv_bfloat16* ga_l = Alo + aoff + kb * 32;
        const __nv_bfloat16* gb_h = Bhi + boff + kb * 32;
        const __nv_bfloat16* gb_l = Blo + boff + kb * 32;
        const uint32_t s = sm0 + (uint32_t)(buf * 4) * (TILE_E * 2) + thr_off;
        CP_ASYNC16(s,                        ga_h);
        CP_ASYNC16(s + 16,                   ga_h + 8);
        CP_ASYNC16(s + TILE_E * 2,           ga_l);
        CP_ASYNC16(s + TILE_E * 2 + 16,      ga_l + 8);
        CP_ASYNC16(s + TILE_E * 4,           gb_h);
        CP_ASYNC16(s + TILE_E * 4 + 16,      gb_h + 8);
        CP_ASYNC16(s + TILE_E * 6,           gb_l);
        CP_ASYNC16(s + TILE_E * 6 + 16,      gb_l + 8);
        CP_COMMIT();
    };

    float acc[4][4][4];
#pragma unroll
    for (int i = 0; i < 4; i++)
#pragma unroll
        for (int j = 0; j < 4; j++)
#pragma unroll
            for (int l = 0; l < 4; l++) acc[i][j][l] = 0.f;

    // ldmatrix per-lane address components
    const int q4     = lane >> 3;
    const int arow_l = (q4 & 1) * 8 + (lane & 7);
    const int akc_l  = (q4 >> 1) * 8;
    const int brow_l = (q4 >> 1) * 8 + (lane & 7);
    const int bkc_l  = (q4 & 1) * 8;

    auto compute = [&](int buf) {
        const uint32_t aH = sm0 + (uint32_t)(buf * 4 + 0) * (TILE_E * 2);
        const uint32_t aL = sm0 + (uint32_t)(buf * 4 + 1) * (TILE_E * 2);
        const uint32_t bH = sm0 + (uint32_t)(buf * 4 + 2) * (TILE_E * 2);
        const uint32_t bL = sm0 + (uint32_t)(buf * 4 + 3) * (TILE_E * 2);
#pragma unroll
        for (int ks = 0; ks < 2; ks++) {
            const uint32_t arow_off =
                (uint32_t)((wr * 64 + arow_l) * SROW + ks * 16 + akc_l) * 2;
            const uint32_t brow_off =
                (uint32_t)((wc * 32 + brow_l) * SROW + ks * 16 + bkc_l) * 2;

            uint32_t ah[4][4], bh[2][4];
#pragma unroll
            for (int mi = 0; mi < 4; mi++)
                LDSM_X4(ah[mi][0], ah[mi][1], ah[mi][2], ah[mi][3],
                        aH + arow_off + mi * 16 * SROW * 2);
#pragma unroll
            for (int nb = 0; nb < 2; nb++)
                LDSM_X4(bh[nb][0], bh[nb][1], bh[nb][2], bh[nb][3],
                        bH + brow_off + nb * 16 * SROW * 2);
            // term 1: hi * hi
#pragma unroll
            for (int mi = 0; mi < 4; mi++)
#pragma unroll
                for (int nb = 0; nb < 2; nb++) {
                    MMA16816(acc[mi][nb * 2 + 0],
                             ah[mi][0], ah[mi][1], ah[mi][2], ah[mi][3],
                             bh[nb][0], bh[nb][1]);
                    MMA16816(acc[mi][nb * 2 + 1],
                             ah[mi][0], ah[mi][1], ah[mi][2], ah[mi][3],
                             bh[nb][2], bh[nb][3]);
                }
            // term 2: lo * hi  (bh still live)
            {
                uint32_t al[4][4];
#pragma unroll
                for (int mi = 0; mi < 4; mi++)
                    LDSM_X4(al[mi][0], al[mi][1], al[mi][2], al[mi][3],
                            aL + arow_off + mi * 16 * SROW * 2);
#pragma unroll
                for (int mi = 0; mi < 4; mi++)
#pragma unroll
                    for (int nb = 0; nb < 2; nb++) {
                        MMA16816(acc[mi][nb * 2 + 0],
                                 al[mi][0], al[mi][1], al[mi][2], al[mi][3],
                                 bh[nb][0], bh[nb][1]);
                        MMA16816(acc[mi][nb * 2 + 1],
                                 al[mi][0], al[mi][1], al[mi][2], al[mi][3],
                                 bh[nb][2], bh[nb][3]);
                    }
            }
            // term 3: hi * lo  (ah still live)
            {
                uint32_t bl[2][4];
#pragma unroll
                for (int nb = 0; nb < 2; nb++)
                    LDSM_X4(bl[nb][0], bl[nb][1], bl[nb][2], bl[nb][3],
                            bL + brow_off + nb * 16 * SROW * 2);
#pragma unroll
                for (int mi = 0; mi < 4; mi++)
#pragma unroll
                    for (int nb = 0; nb < 2; nb++) {
                        MMA16816(acc[mi][nb * 2 + 0],
                                 ah[mi][0], ah[mi][1], ah[mi][2], ah[mi][3],
                                 bl[nb][0], bl[nb][1]);
                        MMA16816(acc[mi][nb * 2 + 1],
                                 ah[mi][0], ah[mi][1], ah[mi][2], ah[mi][3],
                                 bl[nb][2], bl[nb][3]);
                    }
            }
        }
    };

    const int nkb = K >> 5;
    issue(0, 0);
    for (int kb = 0; kb < nkb; kb++) {
        if (kb + 1 < nkb) {
            issue((kb + 1) & 1, kb + 1);
            asm volatile("cp.async.wait_group 1;" ::: "memory");
        } else {
            asm volatile("cp.async.wait_group 0;" ::: "memory");
        }
        __syncthreads();
        compute(kb & 1);
        __syncthreads();
    }

    // ---- epilogue ----
    const int r4 = lane >> 2;
    const int c2 = (lane & 3) * 2;
#pragma unroll
    for (int mi = 0; mi < 4; mi++) {
#pragma unroll
        for (int half = 0; half < 2; half++) {
            const int row = bm * 128 + wr * 64 + mi * 16 + r4 + half * 8;
#pragma unroll
            for (int ni = 0; ni < 4; ni++) {
                const int col = bn * 128 + wc * 32 + ni * 8 + c2;
                float v0 = acc[mi][ni][half * 2 + 0];
                float v1 = acc[mi][ni][half * 2 + 1];
                if (EPI == 1) {
                    v0 = fmaxf(v0 + bias[col],     0.f);
                    v1 = fmaxf(v1 + bias[col + 1], 0.f);
                    __nv_bfloat16 h0, h1, l0, l1;
                    bsplit(v0, h0, l0); bsplit(v1, h1, l1);
                    *(__nv_bfloat162*)(Chi + (size_t)row * N + col) = __halves2bfloat162(h0, h1);
                    *(__nv_bfloat162*)(Clo + (size_t)row * N + col) = __halves2bfloat162(l0, l1);
                } else {
                    if (EPI == 2) { v0 += bias[col]; v1 += bias[col + 1]; }
                    if (EPI == 2 || EPI == 3) {
                        const float2 rv = *(const float2*)(res + (size_t)row * N + col);
                        v0 += rv.x; v1 += rv.y;
                    }
                    *(float2*)(C + (size_t)row * N + col) = make_float2(v0, v1);
                }
            }
        }
    }
}

// ===========================================================================
// Row reciprocal norms: X is [nrows, 64]; out[row] = scale / ||X[row,:]||.
// ===========================================================================
__global__ __launch_bounds__(256)
void rownorm64_k(const float* __restrict__ X, float* __restrict__ out,
                 int nrows, float scale)
{
    const int t   = threadIdx.x;
    const int grp = t >> 4;
    const int ln  = t & 15;
    const int row = blockIdx.x * 16 + grp;
    if (row >= nrows) return;
    const float4 v = *(const float4*)(X + (size_t)row * 64 + ln * 4);
    float ss = v.x * v.x + v.y * v.y + v.z * v.z + v.w * v.w;
#pragma unroll
    for (int o = 8; o > 0; o >>= 1) ss += __shfl_xor_sync(0xffffffffu, ss, o);
    if (ln == 0) out[row] = scale * rsqrtf(fmaxf(ss, 1e-24f));
}

// ===========================================================================
// Fused cosine-similarity attention.
// x = dot(q,k)/(8*|q||k|), |x| <= 0.125 exactly -> degree-5 Taylor exp
// (rel err ~6e-9), zero MUFU in the hot loop. RQ=0.125/|q| folded into q regs.
// Output written as bf16 hi/lo split (feeds O-projection GEMM).
// ===========================================================================
__global__ __launch_bounds__(128)
void attn_k(const float* __restrict__ Q, const float* __restrict__ Km,
            const float* __restrict__ V, const float* __restrict__ RQ,
            const float* __restrict__ RK,
            __nv_bfloat16* __restrict__ Ohi, __nv_bfloat16* __restrict__ Olo)
{
    __shared__ float Ks[64][64];
    __shared__ float Vs[64][64];
    __shared__ float rks[64];

    const int tid = threadIdx.x;
    const int b = blockIdx.z;
    const int h = blockIdx.y;
    const int r = blockIdx.x * 128 + tid;

    const size_t qoff = ((size_t)(b * SS + r) * HH + h) * 64;
    const float myrq = RQ[(size_t)(b * SS + r) * HH + h];   // 0.125/|q|
    float4 qv[16];
#pragma unroll
    for (int i = 0; i < 16; i++) {
        qv[i] = *(const float4*)(Q + qoff + i * 4);
        qv[i].x *= myrq; qv[i].y *= myrq; qv[i].z *= myrq; qv[i].w *= myrq;
    }

    float acc[64];
#pragma unroll
    for (int i = 0; i < 64; i++) acc[i] = 0.f;
    float lsum = 0.f;

    const int j2   = tid >> 1;
    const int part = tid & 1;

    for (int kt = 0; kt < SS / 64; kt++) {
        __syncthreads();
        const size_t kbase =
            ((size_t)(b * SS + kt * 64 + j2) * HH + h) * 64 + part * 32;
#pragma unroll
        for (int i = 0; i < 8; i++) {
            *(float4*)&Ks[j2][part * 32 + i * 4] = *(const float4*)(Km + kbase + i * 4);
            *(float4*)&Vs[j2][part * 32 + i * 4] = *(const float4*)(V  + kbase + i * 4);
        }
        if (tid < 64)
            rks[tid] = RK[(size_t)(b * SS + kt * 64 + tid) * HH + h];
        __syncthreads();

#pragma unroll 2
        for (int j = 0; j < 64; j++) {
            float s = 0.f;
#pragma unroll
            for (int i = 0; i < 16; i++) {
                const float4 kv = *(const float4*)&Ks[j][i * 4];
                s = fmaf(qv[i].x, kv.x, s);
                s = fmaf(qv[i].y, kv.y, s);
                s = fmaf(qv[i].z, kv.z, s);
                s = fmaf(qv[i].w, kv.w, s);
            }
            const float x = s * rks[j];           // |x| <= 0.125
            float p = fmaf(8.3333333e-3f, x, 4.1666667e-2f);
            p = fmaf(p, x, 0.16666667f);
            p = fmaf(p, x, 0.5f);
            p = fmaf(p, x, 1.0f);
            p = fmaf(p, x, 1.0f);                 // exp(x), rel err ~6e-9
            lsum += p;
#pragma unroll
            for (int i = 0; i < 16; i++) {
                const float4 vv = *(const float4*)&Vs[j][i * 4];
                acc[i * 4 + 0] = fmaf(p, vv.x, acc[i * 4 + 0]);
                acc[i * 4 + 1] = fmaf(p, vv.y, acc[i * 4 + 1]);
                acc[i * 4 + 2] = fmaf(p, vv.z, acc[i * 4 + 2]);
                acc[i * 4 + 3] = fmaf(p, vv.w, acc[i * 4 + 3]);
            }
        }
    }

    const float inv = 1.f / lsum;
    __nv_bfloat162* Oh2 = (__nv_bfloat162*)Ohi;
    __nv_bfloat162* Ol2 = (__nv_bfloat162*)Olo;
    const size_t o2 = qoff >> 1;
#pragma unroll
    for (int i = 0; i < 16; i++) {
        const float o0 = acc[i * 4 + 0] * inv;
        const float o1 = acc[i * 4 + 1] * inv;
        const float o2v = acc[i * 4 + 2] * inv;
        const float o3 = acc[i * 4 + 3] * inv;
        __nv_bfloat16 h0, h1, h2, h3, l0, l1, l2, l3;
        bsplit(o0, h0, l0); bsplit(o1, h1, l1);
        bsplit(o2v, h2, l2); bsplit(o3, h3, l3);
        Oh2[o2 + i * 2]     = __halves2bfloat162(h0, h1);
        Oh2[o2 + i * 2 + 1] = __halves2bfloat162(h2, h3);
        Ol2[o2 + i * 2]     = __halves2bfloat162(l0, l1);
        Ol2[o2 + i * 2 + 1] = __halves2bfloat162(l2, l3);
    }
}

// ===========================================================================
// LayerNorm over last dim (512), optional fused bf16 hi/lo split output.
// ===========================================================================
__global__ __launch_bounds__(128)
void ln_k(const float* __restrict__ X, const float* __restrict__ gamma,
          const float* __restrict__ beta, float* __restrict__ out,
          __nv_bfloat16* __restrict__ hi, __nv_bfloat16* __restrict__ lo)
{
    __shared__ float s_sum[4], s_ss[4];
    const int tid = threadIdx.x;
    const size_t row = blockIdx.x;

    const float4 v = *(const float4*)(X + row * 512 + tid * 4);
    float sum = v.x + v.y + v.z + v.w;
    float ss  = v.x * v.x + v.y * v.y + v.z * v.z + v.w * v.w;
#pragma unroll
    for (int o = 16; o > 0; o >>= 1) {
        sum += __shfl_xor_sync(0xffffffffu, sum, o);
        ss  += __shfl_xor_sync(0xffffffffu, ss,  o);
    }
    if ((tid & 31) == 0) { s_sum[tid >> 5] = sum; s_ss[tid >> 5] = ss; }
    __syncthreads();
    sum = s_sum[0] + s_sum[1] + s_sum[2] + s_sum[3];
    ss  = s_ss[0]  + s_ss[1]  + s_ss[2]  + s_ss[3];

    const float mean = sum * (1.f / 512.f);
    const float var  = ss * (1.f / 512.f) - mean * mean;
    const float rstd = rsqrtf(var + 1e-5f);

    const int c = tid * 4;
    const float4 gv = *(const float4*)(gamma + c);
    const float4 bv = *(const float4*)(beta + c);
    float4 o4;
    o4.x = (v.x - mean) * rstd * gv.x + bv.x;
    o4.y = (v.y - mean) * rstd * gv.y + bv.y;
    o4.z = (v.z - mean) * rstd * gv.z + bv.z;
    o4.w = (v.w - mean) * rstd * gv.w + bv.w;
    *(float4*)(out + row * 512 + c) = o4;

    if (hi != nullptr) {
        __nv_bfloat16 h0, h1, h2, h3, l0, l1, l2, l3;
        bsplit(o4.x, h0, l0); bsplit(o4.y, h1, l1);
        bsplit(o4.z, h2, l2); bsplit(o4.w, h3, l3);
        const size_t i2 = row * 256 + tid * 2;
        ((__nv_bfloat162*)hi)[i2]     = __halves2bfloat162(h0, h1);
        ((__nv_bfloat162*)hi)[i2 + 1] = __halves2bfloat162(h2, h3);
        ((__nv_bfloat162*)lo)[i2]     = __halves2bfloat162(l0, l1);
        ((__nv_bfloat162*)lo)[i2 + 1] = __halves2bfloat162(l2, l3);
    }
}

// ===========================================================================
// Launch sequence
// ===========================================================================
extern "C" void kernel_launch(void* const* d_in, const int* in_sizes, int n_in,
                              void* d_out, int out_size)
{
    const float* x     = (const float*)d_in[0];
    const float* w_q   = (const float*)d_in[1];
    const float* w_k   = (const float*)d_in[2];
    const float* w_v   = (const float*)d_in[3];
    const float* w_o   = (const float*)d_in[4];
    const float* w_ff1 = (const float*)d_in[5];
    const float* b_ff1 = (const float*)d_in[6];
    const float* w_ff2 = (const float*)d_in[7];
    const float* b_ff2 = (const float*)d_in[8];
    const float* g1    = (const float*)d_in[9];
    const float* b1    = (const float*)d_in[10];
    const float* g2    = (const float*)d_in[11];
    const float* b2    = (const float*)d_in[12];
    float* out = (float*)d_out;

    __nv_bfloat16 *xh, *xl, *wqh, *wql, *wkh, *wkl, *wvh, *wvl, *woh, *wol;
    __nv_bfloat16 *w1h, *w1l, *w2h, *w2l, *ath, *atl, *h1h, *h1l, *ffh, *ffl;
    float *q, *k, *v, *rq, *rk, *t1, *h1, *t2;
    cudaGetSymbolAddress((void**)&xh,  g_xh);  cudaGetSymbolAddress((void**)&xl,  g_xl);
    cudaGetSymbolAddress((void**)&wqh, g_wqh); cudaGetSymbolAddress((void**)&wql, g_wql);
    cudaGetSymbolAddress((void**)&wkh, g_wkh); cudaGetSymbolAddress((void**)&wkl, g_wkl);
    cudaGetSymbolAddress((void**)&wvh, g_wvh); cudaGetSymbolAddress((void**)&wvl, g_wvl);
    cudaGetSymbolAddress((void**)&woh, g_woh); cudaGetSymbolAddress((void**)&wol, g_wol);
    cudaGetSymbolAddress((void**)&w1h, g_w1h); cudaGetSymbolAddress((void**)&w1l, g_w1l);
    cudaGetSymbolAddress((void**)&w2h, g_w2h); cudaGetSymbolAddress((void**)&w2l, g_w2l);
    cudaGetSymbolAddress((void**)&ath, g_ath); cudaGetSymbolAddress((void**)&atl, g_atl);
    cudaGetSymbolAddress((void**)&h1h, g_h1h); cudaGetSymbolAddress((void**)&h1l, g_h1l);
    cudaGetSymbolAddress((void**)&ffh, g_ffh); cudaGetSymbolAddress((void**)&ffl, g_ffl);
    cudaGetSymbolAddress((void**)&q,  g_q);  cudaGetSymbolAddress((void**)&k,  g_k);
    cudaGetSymbolAddress((void**)&v,  g_v);  cudaGetSymbolAddress((void**)&rq, g_rq);
    cudaGetSymbolAddress((void**)&rk, g_rk); cudaGetSymbolAddress((void**)&t1, g_t1);
    cudaGetSymbolAddress((void**)&h1, g_h1); cudaGetSymbolAddress((void**)&t2, g_t2);

    cudaFuncSetAttribute(mgemm_k<0>, cudaFuncAttributeMaxDynamicSharedMemorySize, MG_SMEM);
    cudaFuncSetAttribute(mgemm_k<1>, cudaFuncAttributeMaxDynamicSharedMemorySize, MG_SMEM);
    cudaFuncSetAttribute(mgemm_k<2>, cudaFuncAttributeMaxDynamicSharedMemorySize, MG_SMEM);
    cudaFuncSetAttribute(mgemm_k<3>, cudaFuncAttributeMaxDynamicSharedMemorySize, MG_SMEM);

    // --- input + weight prep ---
    const int n4 = MM * DDIM / 4;
    split_k<<<n4 / 256, 256>>>((const float4*)x, (__nv_bfloat162*)xh,
                               (__nv_bfloat162*)xl, n4);
    tsplit_k<<<dim3(DDIM / 32, DDIM / 32), 256>>>(w_q,   wqh, wql, DDIM, DDIM);
    tsplit_k<<<dim3(DDIM / 32, DDIM / 32), 256>>>(w_k,   wkh, wkl, DDIM, DDIM);
    tsplit_k<<<dim3(DDIM / 32, DDIM / 32), 256>>>(w_v,   wvh, wvl, DDIM, DDIM);
    tsplit_k<<<dim3(DDIM / 32, DDIM / 32), 256>>>(w_o,   woh, wol, DDIM, DDIM);
    tsplit_k<<<dim3(DFFN / 32, DDIM / 32), 256>>>(w_ff1, w1h, w1l, DDIM, DFFN);
    tsplit_k<<<dim3(DDIM / 32, DFFN / 32), 256>>>(w_ff2, w2h, w2l, DFFN, DDIM);

    const dim3 g512(DDIM / 128, MM / 128);   // (4, 128)
    const dim3 gff1(DFFN / 128, MM / 128);   // (16, 128)

    // --- Q/K/V projections (fp32 out, [16384,512] == [b,s,h,dk]) ---
    mgemm_k<0><<<g512, 256, MG_SMEM>>>(xh, xl, wqh, wql, q, MM, DDIM, DDIM,
                                       nullptr, nullptr, nullptr, nullptr);
    mgemm_k<0><<<g512, 256, MG_SMEM>>>(xh, xl, wkh, wkl, k, MM, DDIM, DDIM,
                                       nullptr, nullptr, nullptr, nullptr);
    mgemm_k<0><<<g512, 256, MG_SMEM>>>(xh, xl, wvh, wvl, v, MM, DDIM, DDIM,
                                       nullptr, nullptr, nullptr, nullptr);

    // --- per-(b,s,h) reciprocal norms (q pre-folds the 1/temp=1/8) ---
    rownorm64_k<<<(MM * HH) / 16, 256>>>(q, rq, MM * HH, 0.125f);
    rownorm64_k<<<(MM * HH) / 16, 256>>>(k, rk, MM * HH, 1.0f);

    // --- fused cosine attention -> bf16 split output ---
    attn_k<<<dim3(SS / 128, HH, BB), 128>>>(q, k, v, rq, rk, ath, atl);

    // --- O-projection + residual x -> t1 ---
    mgemm_k<3><<<g512, 256, MG_SMEM>>>(ath, atl, woh, wol, t1, MM, DDIM, DDIM,
                                       nullptr, x, nullptr, nullptr);

    // --- LN1 -> h1 (fp32) + bf16 split ---
    ln_k<<<MM, 128>>>(t1, g1, b1, h1, h1h, h1l);

    // --- FFN1 + bias + relu -> bf16 split only ---
    mgemm_k<1><<<gff1, 256, MG_SMEM>>>(h1h, h1l, w1h, w1l, nullptr, MM, DFFN, DDIM,
                                       b_ff1, nullptr, ffh, ffl);

    // --- FFN2 + bias + residual h1 -> t2 ---
    mgemm_k<2><<<g512, 256, MG_SMEM>>>(ffh, ffl, w2h, w2l, t2, MM, DDIM, DFFN,
                                       b_ff2, h1, nullptr, nullptr);

    // --- LN2 -> output ---
    ln_k<<<MM, 128>>>(t2, g2, b2, out, nullptr, nullptr);
}

// round 8
// speedup vs baseline: 2.6434x; 1.5352x over previous
#include <cuda_runtime.h>
#include <cuda_bf16.h>
#include <cstdint>

// Problem constants
#define BB   32
#define SS   512
#define DDIM 512
#define HH   8
#define MM   (BB * SS)     // 16384 tokens
#define DFFN 2048

// ===========================================================================
// PTX helpers (baseline ISA only — harness compiles for compute_103, which
// rejects sm_103a-variant instructions like tcgen05/TMEM)
// ===========================================================================
__device__ __forceinline__ uint32_t smem_to_u32(const void* p) {
    uint32_t a;
    asm("{ .reg .u64 t; cvta.to.shared.u64 t, %1; cvt.u32.u64 %0, t; }"
        : "=r"(a) : "l"(p));
    return a;
}

#define CP_ASYNC16(smem, gptr) \
    asm volatile("cp.async.cg.shared.global [%0], [%1], 16;" \
        :: "r"(smem), "l"(gptr) : "memory")
#define CP_COMMIT() asm volatile("cp.async.commit_group;" ::: "memory")

#define LDSM_X4(r0, r1, r2, r3, addr) \
    asm volatile("ldmatrix.sync.aligned.m8n8.x4.shared.b16 {%0,%1,%2,%3}, [%4];" \
        : "=r"(r0), "=r"(r1), "=r"(r2), "=r"(r3) : "r"(addr))

#define MMA16816(d, a0, a1, a2, a3, b0, b1) \
    asm volatile("mma.sync.aligned.m16n8k16.row.col.f32.bf16.bf16.f32 " \
        "{%0,%1,%2,%3}, {%4,%5,%6,%7}, {%8,%9}, {%0,%1,%2,%3};" \
        : "+f"((d)[0]), "+f"((d)[1]), "+f"((d)[2]), "+f"((d)[3]) \
        : "r"(a0), "r"(a1), "r"(a2), "r"(a3), "r"(b0), "r"(b1))

__device__ __forceinline__ uint32_t pack_bf16x2(float lo, float hi) {
    __nv_bfloat162 t = __floats2bfloat162_rn(lo, hi);   // .x = lo (low half)
    return *(uint32_t*)&t;
}

// ===========================================================================
// Scratch (device globals)
// ===========================================================================
__device__ __nv_bfloat16 g_xh [MM * DDIM], g_xl [MM * DDIM];
__device__ __nv_bfloat16 g_wqh[DDIM * DDIM], g_wql[DDIM * DDIM];
__device__ __nv_bfloat16 g_wkh[DDIM * DDIM], g_wkl[DDIM * DDIM];
__device__ __nv_bfloat16 g_wvh[DDIM * DDIM], g_wvl[DDIM * DDIM];
__device__ __nv_bfloat16 g_woh[DDIM * DDIM], g_wol[DDIM * DDIM];
__device__ __nv_bfloat16 g_w1h[DFFN * DDIM], g_w1l[DFFN * DDIM];
__device__ __nv_bfloat16 g_w2h[DDIM * DFFN], g_w2l[DDIM * DFFN];
__device__ __nv_bfloat16 g_ath[MM * DDIM], g_atl[MM * DDIM];
__device__ __nv_bfloat16 g_h1h[MM * DDIM], g_h1l[MM * DDIM];
__device__ __nv_bfloat16 g_ffh[(size_t)MM * DFFN], g_ffl[(size_t)MM * DFFN];
__device__ __nv_bfloat16 g_qn [MM * DDIM], g_kn [MM * DDIM], g_vt [MM * DDIM];
__device__ float g_q [MM * DDIM], g_k [MM * DDIM], g_v [MM * DDIM];
__device__ float g_t1[MM * DDIM], g_h1[MM * DDIM], g_t2[MM * DDIM];

__device__ __forceinline__ void bsplit(float x, __nv_bfloat16& hi, __nv_bfloat16& lo) {
    hi = __float2bfloat16(x);
    lo = __float2bfloat16(x - __bfloat162float(hi));
}

// ===========================================================================
// fp32 -> bf16 hi/lo split (elementwise)
// ===========================================================================
__global__ __launch_bounds__(256)
void split_k(const float4* __restrict__ X, __nv_bfloat162* __restrict__ Hi,
             __nv_bfloat162* __restrict__ Lo, int n4)
{
    int i = blockIdx.x * 256 + threadIdx.x;
    if (i >= n4) return;
    float4 v = X[i];
    __nv_bfloat16 h0, h1, h2, h3, l0, l1, l2, l3;
    bsplit(v.x, h0, l0); bsplit(v.y, h1, l1);
    bsplit(v.z, h2, l2); bsplit(v.w, h3, l3);
    Hi[i * 2]     = __halves2bfloat162(h0, h1);
    Hi[i * 2 + 1] = __halves2bfloat162(h2, h3);
    Lo[i * 2]     = __halves2bfloat162(l0, l1);
    Lo[i * 2 + 1] = __halves2bfloat162(l2, l3);
}

// ===========================================================================
// Weight transpose + split: W[K,N] fp32 -> Thi/Tlo [N,K] bf16 (K-major)
// ===========================================================================
__global__ __launch_bounds__(256)
void tsplit_k(const float* __restrict__ W, __nv_bfloat16* __restrict__ Thi,
              __nv_bfloat16* __restrict__ Tlo, int K, int N)
{
    __shared__ float t[32][33];
    const int tx = threadIdx.x & 31, ty = threadIdx.x >> 5;
    const int n0 = blockIdx.x * 32, k0 = blockIdx.y * 32;
#pragma unroll
    for (int j = 0; j < 4; j++)
        t[ty + j * 8][tx] = W[(size_t)(k0 + ty + j * 8) * N + n0 + tx];
    __syncthreads();
#pragma unroll
    for (int j = 0; j < 4; j++) {
        const float v = t[tx][ty + j * 8];
        __nv_bfloat16 hi, lo;
        bsplit(v, hi, lo);
        const size_t o = (size_t)(n0 + ty + j * 8) * K + k0 + tx;
        Thi[o] = hi; Tlo[o] = lo;
    }
}

// ===========================================================================
// bf16-split HMMA GEMM (unchanged from R6 — verified):
// C[M,N] = (Ahi+Alo)[M,K] @ (Bhi+Blo)[N,K]^T, 3-term split, fp32 acc.
// ===========================================================================
#define SROW   40
#define TILE_E (128 * SROW)
static constexpr int MG_SMEM = 2 * 4 * TILE_E * 2;   // 81920 B

template <int EPI>
__global__ __launch_bounds__(256, 2)
void mgemm_k(const __nv_bfloat16* __restrict__ Ahi, const __nv_bfloat16* __restrict__ Alo,
             const __nv_bfloat16* __restrict__ Bhi, const __nv_bfloat16* __restrict__ Blo,
             float* __restrict__ C, int M, int N, int K,
             const float* __restrict__ bias, const float* __restrict__ res,
             __nv_bfloat16* __restrict__ Chi, __nv_bfloat16* __restrict__ Clo)
{
    extern __shared__ __nv_bfloat16 sm[];
    const uint32_t sm0 = smem_to_u32(sm);

    const int tid  = threadIdx.x;
    const int wid  = tid >> 5, lane = tid & 31;
    const int wr   = wid >> 2, wc = wid & 3;
    const int bm   = blockIdx.y, bn = blockIdx.x;

    const int lrow = tid >> 1;
    const int lkc0 = (tid & 1) * 2;

    const size_t aoff = (size_t)(bm * 128 + lrow) * K + lkc0 * 8;
    const size_t boff = (size_t)(bn * 128 + lrow) * K + lkc0 * 8;
    const uint32_t thr_off = (uint32_t)(lrow * SROW + lkc0 * 8) * 2;

    auto issue = [&](int buf, int kb) {
        const __nv_bfloat16* ga_h = Ahi + aoff + kb * 32;
        const __nv_bfloat16* ga_l = Alo + aoff + kb * 32;
        const __nv_bfloat16* gb_h = Bhi + boff + kb * 32;
        const __nv_bfloat16* gb_l = Blo + boff + kb * 32;
        const uint32_t s = sm0 + (uint32_t)(buf * 4) * (TILE_E * 2) + thr_off;
        CP_ASYNC16(s,                        ga_h);
        CP_ASYNC16(s + 16,                   ga_h + 8);
        CP_ASYNC16(s + TILE_E * 2,           ga_l);
        CP_ASYNC16(s + TILE_E * 2 + 16,      ga_l + 8);
        CP_ASYNC16(s + TILE_E * 4,           gb_h);
        CP_ASYNC16(s + TILE_E * 4 + 16,      gb_h + 8);
        CP_ASYNC16(s + TILE_E * 6,           gb_l);
        CP_ASYNC16(s + TILE_E * 6 + 16,      gb_l + 8);
        CP_COMMIT();
    };

    float acc[4][4][4];
#pragma unroll
    for (int i = 0; i < 4; i++)
#pragma unroll
        for (int j = 0; j < 4; j++)
#pragma unroll
            for (int l = 0; l < 4; l++) acc[i][j][l] = 0.f;

    const int q4     = lane >> 3;
    const int arow_l = (q4 & 1) * 8 + (lane & 7);
    const int akc_l  = (q4 >> 1) * 8;
    const int brow_l = (q4 >> 1) * 8 + (lane & 7);
    const int bkc_l  = (q4 & 1) * 8;

    auto compute = [&](int buf) {
        const uint32_t aH = sm0 + (uint32_t)(buf * 4 + 0) * (TILE_E * 2);
        const uint32_t aL = sm0 + (uint32_t)(buf * 4 + 1) * (TILE_E * 2);
        const uint32_t bH = sm0 + (uint32_t)(buf * 4 + 2) * (TILE_E * 2);
        const uint32_t bL = sm0 + (uint32_t)(buf * 4 + 3) * (TILE_E * 2);
#pragma unroll
        for (int ks = 0; ks < 2; ks++) {
            const uint32_t arow_off =
                (uint32_t)((wr * 64 + arow_l) * SROW + ks * 16 + akc_l) * 2;
            const uint32_t brow_off =
                (uint32_t)((wc * 32 + brow_l) * SROW + ks * 16 + bkc_l) * 2;

            uint32_t ah[4][4], bh[2][4];
#pragma unroll
            for (int mi = 0; mi < 4; mi++)
                LDSM_X4(ah[mi][0], ah[mi][1], ah[mi][2], ah[mi][3],
                        aH + arow_off + mi * 16 * SROW * 2);
#pragma unroll
            for (int nb = 0; nb < 2; nb++)
                LDSM_X4(bh[nb][0], bh[nb][1], bh[nb][2], bh[nb][3],
                        bH + brow_off + nb * 16 * SROW * 2);
#pragma unroll
            for (int mi = 0; mi < 4; mi++)
#pragma unroll
                for (int nb = 0; nb < 2; nb++) {
                    MMA16816(acc[mi][nb * 2 + 0],
                             ah[mi][0], ah[mi][1], ah[mi][2], ah[mi][3],
                             bh[nb][0], bh[nb][1]);
                    MMA16816(acc[mi][nb * 2 + 1],
                             ah[mi][0], ah[mi][1], ah[mi][2], ah[mi][3],
                             bh[nb][2], bh[nb][3]);
                }
            {
                uint32_t al[4][4];
#pragma unroll
                for (int mi = 0; mi < 4; mi++)
                    LDSM_X4(al[mi][0], al[mi][1], al[mi][2], al[mi][3],
                            aL + arow_off + mi * 16 * SROW * 2);
#pragma unroll
                for (int mi = 0; mi < 4; mi++)
#pragma unroll
                    for (int nb = 0; nb < 2; nb++) {
                        MMA16816(acc[mi][nb * 2 + 0],
                                 al[mi][0], al[mi][1], al[mi][2], al[mi][3],
                                 bh[nb][0], bh[nb][1]);
                        MMA16816(acc[mi][nb * 2 + 1],
                                 al[mi][0], al[mi][1], al[mi][2], al[mi][3],
                                 bh[nb][2], bh[nb][3]);
                    }
            }
            {
                uint32_t bl[2][4];
#pragma unroll
                for (int nb = 0; nb < 2; nb++)
                    LDSM_X4(bl[nb][0], bl[nb][1], bl[nb][2], bl[nb][3],
                            bL + brow_off + nb * 16 * SROW * 2);
#pragma unroll
                for (int mi = 0; mi < 4; mi++)
#pragma unroll
                    for (int nb = 0; nb < 2; nb++) {
                        MMA16816(acc[mi][nb * 2 + 0],
                                 ah[mi][0], ah[mi][1], ah[mi][2], ah[mi][3],
                                 bl[nb][0], bl[nb][1]);
                        MMA16816(acc[mi][nb * 2 + 1],
                                 ah[mi][0], ah[mi][1], ah[mi][2], ah[mi][3],
                                 bl[nb][2], bl[nb][3]);
                    }
            }
        }
    };

    const int nkb = K >> 5;
    issue(0, 0);
    for (int kb = 0; kb < nkb; kb++) {
        if (kb + 1 < nkb) {
            issue((kb + 1) & 1, kb + 1);
            asm volatile("cp.async.wait_group 1;" ::: "memory");
        } else {
            asm volatile("cp.async.wait_group 0;" ::: "memory");
        }
        __syncthreads();
        compute(kb & 1);
        __syncthreads();
    }

    const int r4 = lane >> 2;
    const int c2 = (lane & 3) * 2;
#pragma unroll
    for (int mi = 0; mi < 4; mi++) {
#pragma unroll
        for (int half = 0; half < 2; half++) {
            const int row = bm * 128 + wr * 64 + mi * 16 + r4 + half * 8;
#pragma unroll
            for (int ni = 0; ni < 4; ni++) {
                const int col = bn * 128 + wc * 32 + ni * 8 + c2;
                float v0 = acc[mi][ni][half * 2 + 0];
                float v1 = acc[mi][ni][half * 2 + 1];
                if (EPI == 1) {
                    v0 = fmaxf(v0 + bias[col],     0.f);
                    v1 = fmaxf(v1 + bias[col + 1], 0.f);
                    __nv_bfloat16 h0, h1, l0, l1;
                    bsplit(v0, h0, l0); bsplit(v1, h1, l1);
                    *(__nv_bfloat162*)(Chi + (size_t)row * N + col) = __halves2bfloat162(h0, h1);
                    *(__nv_bfloat162*)(Clo + (size_t)row * N + col) = __halves2bfloat162(l0, l1);
                } else {
                    if (EPI == 2) { v0 += bias[col]; v1 += bias[col + 1]; }
                    if (EPI == 2 || EPI == 3) {
                        const float2 rv = *(const float2*)(res + (size_t)row * N + col);
                        v0 += rv.x; v1 += rv.y;
                    }
                    *(float2*)(C + (size_t)row * N + col) = make_float2(v0, v1);
                }
            }
        }
    }
}

// ===========================================================================
// Fused row-normalize + bf16 convert: X [nrows,64] fp32 ->
// Out[row,:] = bf16( X[row,:] * scale / ||X[row,:]|| )
// ===========================================================================
__global__ __launch_bounds__(256)
void qknorm_k(const float* __restrict__ X, __nv_bfloat16* __restrict__ Out,
              int nrows, float scale)
{
    const int t   = threadIdx.x;
    const int grp = t >> 4;
    const int ln  = t & 15;
    const int row = blockIdx.x * 16 + grp;
    if (row >= nrows) return;
    const float4 v = *(const float4*)(X + (size_t)row * 64 + ln * 4);
    float ss = v.x * v.x + v.y * v.y + v.z * v.z + v.w * v.w;
#pragma unroll
    for (int o = 8; o > 0; o >>= 1) ss += __shfl_xor_sync(0xffffffffu, ss, o);
    const float sc = scale * rsqrtf(fmaxf(ss, 1e-24f));
    __nv_bfloat162* o2 = (__nv_bfloat162*)(Out + (size_t)row * 64 + ln * 4);
    o2[0] = __floats2bfloat162_rn(v.x * sc, v.y * sc);
    o2[1] = __floats2bfloat162_rn(v.z * sc, v.w * sc);
}

// ===========================================================================
// V transpose + convert: v fp32 [b,s,h,d] -> vt bf16 [b,h,d,s]
// ===========================================================================
__global__ __launch_bounds__(256)
void vtrans_k(const float* __restrict__ V, __nv_bfloat16* __restrict__ Vt)
{
    __shared__ float t[64][65];
    const int tid = threadIdx.x;
    const int st = blockIdx.x;        // s-tile 0..7
    const int h  = blockIdx.y, b = blockIdx.z;
    const int r16 = tid >> 4;         // 0..15
    const int c16 = tid & 15;
#pragma unroll
    for (int it = 0; it < 4; it++) {
        const int s = it * 16 + r16;
        const float4 v4 = *(const float4*)(
            V + ((size_t)(b * SS + st * 64 + s) * HH + h) * 64 + c16 * 4);
        t[s][c16 * 4 + 0] = v4.x; t[s][c16 * 4 + 1] = v4.y;
        t[s][c16 * 4 + 2] = v4.z; t[s][c16 * 4 + 3] = v4.w;
    }
    __syncthreads();
#pragma unroll
    for (int it = 0; it < 4; it++) {
        const int d = it * 16 + r16;
        const int s0 = c16 * 4;
        const size_t o = ((size_t)((b * HH + h) * 64 + d)) * SS + st * 64 + s0;
        *(__nv_bfloat162*)(Vt + o)     = __floats2bfloat162_rn(t[s0][d],     t[s0 + 1][d]);
        *(__nv_bfloat162*)(Vt + o + 2) = __floats2bfloat162_rn(t[s0 + 2][d], t[s0 + 3][d]);
    }
}

// ===========================================================================
// Flash-style HMMA cosine attention.
// Inputs pre-normalized: Qn = q*0.125/|q|, Kn = k/|k| (bf16, [b,s,h,d]);
// Vt = V^T (bf16, [b,h,d,s]). Scores |x| <= 0.125 -> NO max subtraction:
// P = taylor_exp(S) on fp32 fragments, row sums accumulated, P repacked
// C-frag -> A-frag (FA2 trick), PV on tensor pipe. Out = bf16 hi/lo split.
// CTA = 64 q-rows, 4 warps x m16; K/V tiles (64) double-buffered cp.async.
// ===========================================================================
#define FSR 72   // smem row stride (144B = 9x16B -> ldmatrix conflict-free)

__global__ __launch_bounds__(128, 4)
void fattn_k(const __nv_bfloat16* __restrict__ Qn, const __nv_bfloat16* __restrict__ Kn,
             const __nv_bfloat16* __restrict__ Vt,
             __nv_bfloat16* __restrict__ Ohi, __nv_bfloat16* __restrict__ Olo)
{
    __shared__ __nv_bfloat16 Qs[64 * FSR];
    __shared__ __nv_bfloat16 Ks[2][64 * FSR];
    __shared__ __nv_bfloat16 Vs[2][64 * FSR];

    const int tid = threadIdx.x, wid = tid >> 5, lane = tid & 31;
    const int b = blockIdx.z, h = blockIdx.y, qt = blockIdx.x;

    // cp.async mapping: row = tid>>1 (0..63), 4x16B chunks at cols cg*8..
    const int row = tid >> 1;
    const int cg  = (tid & 1) * 4;

    const size_t qbase = ((size_t)(b * SS + qt * 64 + row) * HH + h) * 64 + cg * 8;
    const size_t kbase = ((size_t)(b * SS + row) * HH + h) * 64 + cg * 8;       // +kt*32768
    const size_t vbase = ((size_t)((b * HH + h) * 64 + row)) * SS + cg * 8;     // +kt*64
    const uint32_t thr_s = (uint32_t)(row * FSR + cg * 8) * 2;
    const uint32_t sQ  = smem_to_u32(Qs)    + thr_s;
    const uint32_t sK0 = smem_to_u32(Ks[0]) + thr_s;
    const uint32_t sV0 = smem_to_u32(Vs[0]) + thr_s;
    const uint32_t bufstep = 64 * FSR * 2;

    // G0: Q + kv tile 0
#pragma unroll
    for (int j = 0; j < 4; j++) CP_ASYNC16(sQ + j * 16, Qn + qbase + j * 8);
#pragma unroll
    for (int j = 0; j < 4; j++) CP_ASYNC16(sK0 + j * 16, Kn + kbase + j * 8);
#pragma unroll
    for (int j = 0; j < 4; j++) CP_ASYNC16(sV0 + j * 16, Vt + vbase + j * 8);
    CP_COMMIT();
    // G1: kv tile 1
#pragma unroll
    for (int j = 0; j < 4; j++) CP_ASYNC16(sK0 + bufstep + j * 16, Kn + kbase + 32768 + j * 8);
#pragma unroll
    for (int j = 0; j < 4; j++) CP_ASYNC16(sV0 + bufstep + j * 16, Vt + vbase + 64 + j * 8);
    CP_COMMIT();

    asm volatile("cp.async.wait_group 1;" ::: "memory");
    __syncthreads();

    // ldmatrix lane addressing (same derivation as mgemm_k — verified)
    const int q4     = lane >> 3;
    const int arow_l = (q4 & 1) * 8 + (lane & 7);
    const int akc_l  = (q4 >> 1) * 8;
    const int brow_l = (q4 >> 1) * 8 + (lane & 7);
    const int bkc_l  = (q4 & 1) * 8;

    // Q fragments: warp wid covers q-rows 16*wid..16*wid+15, k = 64 dims
    uint32_t qa[4][4];
    {
        const uint32_t qb = smem_to_u32(Qs);
#pragma unroll
        for (int ks = 0; ks < 4; ks++)
            LDSM_X4(qa[ks][0], qa[ks][1], qa[ks][2], qa[ks][3],
                    qb + (uint32_t)((wid * 16 + arow_l) * FSR + ks * 16 + akc_l) * 2);
    }

    float oacc[4][2][4];
#pragma unroll
    for (int i = 0; i < 4; i++)
#pragma unroll
        for (int j = 0; j < 2; j++)
#pragma unroll
            for (int l = 0; l < 4; l++) oacc[i][j][l] = 0.f;
    float lsum0 = 0.f, lsum1 = 0.f;

    for (int kt = 0; kt < 8; kt++) {
        const int cur = kt & 1;
        const uint32_t kbS = smem_to_u32(Ks[cur]);
        const uint32_t vbS = smem_to_u32(Vs[cur]);

        // ---- S = Qn @ Kn^T (64 keys of this tile) ----
        float sacc[4][2][4];
#pragma unroll
        for (int i = 0; i < 4; i++)
#pragma unroll
            for (int j = 0; j < 2; j++)
#pragma unroll
                for (int l = 0; l < 4; l++) sacc[i][j][l] = 0.f;
#pragma unroll
        for (int ks = 0; ks < 4; ks++) {
            uint32_t kf[4][4];
#pragma unroll
            for (int nb = 0; nb < 4; nb++)
                LDSM_X4(kf[nb][0], kf[nb][1], kf[nb][2], kf[nb][3],
                        kbS + (uint32_t)((nb * 16 + brow_l) * FSR + ks * 16 + bkc_l) * 2);
#pragma unroll
            for (int nb = 0; nb < 4; nb++) {
                MMA16816(sacc[nb][0], qa[ks][0], qa[ks][1], qa[ks][2], qa[ks][3],
                         kf[nb][0], kf[nb][1]);
                MMA16816(sacc[nb][1], qa[ks][0], qa[ks][1], qa[ks][2], qa[ks][3],
                         kf[nb][2], kf[nb][3]);
            }
        }

        // ---- P = exp(S) via Taylor (|S| <= 0.125), lsum, pack C->A frags ----
        uint32_t pa[4][4];
#pragma unroll
        for (int nb = 0; nb < 4; nb++) {
#pragma unroll
            for (int h2 = 0; h2 < 2; h2++)
#pragma unroll
                for (int e = 0; e < 4; e++) {
                    const float x = sacc[nb][h2][e];
                    float p = fmaf(8.3333333e-3f, x, 4.1666667e-2f);
                    p = fmaf(p, x, 0.16666667f);
                    p = fmaf(p, x, 0.5f);
                    p = fmaf(p, x, 1.0f);
                    p = fmaf(p, x, 1.0f);
                    sacc[nb][h2][e] = p;
                }
            lsum0 += sacc[nb][0][0] + sacc[nb][0][1] + sacc[nb][1][0] + sacc[nb][1][1];
            lsum1 += sacc[nb][0][2] + sacc[nb][0][3] + sacc[nb][1][2] + sacc[nb][1][3];
            pa[nb][0] = pack_bf16x2(sacc[nb][0][0], sacc[nb][0][1]);   // row r4,   k 0..7
            pa[nb][1] = pack_bf16x2(sacc[nb][0][2], sacc[nb][0][3]);   // row r4+8, k 0..7
            pa[nb][2] = pack_bf16x2(sacc[nb][1][0], sacc[nb][1][1]);   // row r4,   k 8..15
            pa[nb][3] = pack_bf16x2(sacc[nb][1][2], sacc[nb][1][3]);   // row r4+8, k 8..15
        }

        // ---- O += P @ V  (B = Vt[d, kpos], same TN ldmatrix pattern) ----
#pragma unroll
        for (int ks2 = 0; ks2 < 4; ks2++) {
            uint32_t vf[4][4];
#pragma unroll
            for (int db = 0; db < 4; db++)
                LDSM_X4(vf[db][0], vf[db][1], vf[db][2], vf[db][3],
                        vbS + (uint32_t)((db * 16 + brow_l) * FSR + ks2 * 16 + bkc_l) * 2);
#pragma unroll
            for (int db = 0; db < 4; db++) {
                MMA16816(oacc[db][0], pa[ks2][0], pa[ks2][1], pa[ks2][2], pa[ks2][3],
                         vf[db][0], vf[db][1]);
                MMA16816(oacc[db][1], pa[ks2][0], pa[ks2][1], pa[ks2][2], pa[ks2][3],
                         vf[db][2], vf[db][3]);
            }
        }

        // ---- prefetch kv(kt+2) into the buffer just consumed ----
        if (kt < 7) {
            __syncthreads();
            if (kt + 2 < 8) {
                const size_t ko = kbase + (size_t)(kt + 2) * 32768;
                const size_t vo = vbase + (kt + 2) * 64;
                const uint32_t sk = sK0 + cur * bufstep;
                const uint32_t sv = sV0 + cur * bufstep;
#pragma unroll
                for (int j = 0; j < 4; j++) CP_ASYNC16(sk + j * 16, Kn + ko + j * 8);
#pragma unroll
                for (int j = 0; j < 4; j++) CP_ASYNC16(sv + j * 16, Vt + vo + j * 8);
                CP_COMMIT();
                asm volatile("cp.async.wait_group 1;" ::: "memory");
            } else {
                asm volatile("cp.async.wait_group 0;" ::: "memory");
            }
            __syncthreads();
        }
    }

    // ---- epilogue: normalize by row sums, bf16 hi/lo split out ----
    lsum0 += __shfl_xor_sync(0xffffffffu, lsum0, 1);
    lsum0 += __shfl_xor_sync(0xffffffffu, lsum0, 2);
    lsum1 += __shfl_xor_sync(0xffffffffu, lsum1, 1);
    lsum1 += __shfl_xor_sync(0xffffffffu, lsum1, 2);
    const float inv0 = 1.f / lsum0;
    const float inv1 = 1.f / lsum1;

    const int r4 = lane >> 2;
    const int c2 = (lane & 3) * 2;
    const int s0 = qt * 64 + wid * 16 + r4;
#pragma unroll
    for (int db = 0; db < 4; db++) {
#pragma unroll
        for (int h2 = 0; h2 < 2; h2++) {
            const int d = db * 16 + h2 * 8 + c2;
            // row s0
            {
                const float v0 = oacc[db][h2][0] * inv0;
                const float v1 = oacc[db][h2][1] * inv0;
                __nv_bfloat16 hh0, hh1, ll0, ll1;
                bsplit(v0, hh0, ll0); bsplit(v1, hh1, ll1);
                const size_t o = ((size_t)(b * SS + s0) * HH + h) * 64 + d;
                *(__nv_bfloat162*)(Ohi + o) = __halves2bfloat162(hh0, hh1);
                *(__nv_bfloat162*)(Olo + o) = __halves2bfloat162(ll0, ll1);
            }
            // row s0 + 8
            {
                const float v0 = oacc[db][h2][2] * inv1;
                const float v1 = oacc[db][h2][3] * inv1;
                __nv_bfloat16 hh0, hh1, ll0, ll1;
                bsplit(v0, hh0, ll0); bsplit(v1, hh1, ll1);
                const size_t o = ((size_t)(b * SS + s0 + 8) * HH + h) * 64 + d;
                *(__nv_bfloat162*)(Ohi + o) = __halves2bfloat162(hh0, hh1);
                *(__nv_bfloat162*)(Olo + o) = __halves2bfloat162(ll0, ll1);
            }
        }
    }
}

// ===========================================================================
// LayerNorm over last dim (512), optional fused bf16 hi/lo split output.
// ===========================================================================
__global__ __launch_bounds__(128)
void ln_k(const float* __restrict__ X, const float* __restrict__ gamma,
          const float* __restrict__ beta, float* __restrict__ out,
          __nv_bfloat16* __restrict__ hi, __nv_bfloat16* __restrict__ lo)
{
    __shared__ float s_sum[4], s_ss[4];
    const int tid = threadIdx.x;
    const size_t row = blockIdx.x;

    const float4 v = *(const float4*)(X + row * 512 + tid * 4);
    float sum = v.x + v.y + v.z + v.w;
    float ss  = v.x * v.x + v.y * v.y + v.z * v.z + v.w * v.w;
#pragma unroll
    for (int o = 16; o > 0; o >>= 1) {
        sum += __shfl_xor_sync(0xffffffffu, sum, o);
        ss  += __shfl_xor_sync(0xffffffffu, ss,  o);
    }
    if ((tid & 31) == 0) { s_sum[tid >> 5] = sum; s_ss[tid >> 5] = ss; }
    __syncthreads();
    sum = s_sum[0] + s_sum[1] + s_sum[2] + s_sum[3];
    ss  = s_ss[0]  + s_ss[1]  + s_ss[2]  + s_ss[3];

    const float mean = sum * (1.f / 512.f);
    const float var  = ss * (1.f / 512.f) - mean * mean;
    const float rstd = rsqrtf(var + 1e-5f);

    const int c = tid * 4;
    const float4 gv = *(const float4*)(gamma + c);
    const float4 bv = *(const float4*)(beta + c);
    float4 o4;
    o4.x = (v.x - mean) * rstd * gv.x + bv.x;
    o4.y = (v.y - mean) * rstd * gv.y + bv.y;
    o4.z = (v.z - mean) * rstd * gv.z + bv.z;
    o4.w = (v.w - mean) * rstd * gv.w + bv.w;
    *(float4*)(out + row * 512 + c) = o4;

    if (hi != nullptr) {
        __nv_bfloat16 h0, h1, h2, h3, l0, l1, l2, l3;
        bsplit(o4.x, h0, l0); bsplit(o4.y, h1, l1);
        bsplit(o4.z, h2, l2); bsplit(o4.w, h3, l3);
        const size_t i2 = row * 256 + tid * 2;
        ((__nv_bfloat162*)hi)[i2]     = __halves2bfloat162(h0, h1);
        ((__nv_bfloat162*)hi)[i2 + 1] = __halves2bfloat162(h2, h3);
        ((__nv_bfloat162*)lo)[i2]     = __halves2bfloat162(l0, l1);
        ((__nv_bfloat162*)lo)[i2 + 1] = __halves2bfloat162(l2, l3);
    }
}

// ===========================================================================
// Launch sequence
// ===========================================================================
extern "C" void kernel_launch(void* const* d_in, const int* in_sizes, int n_in,
                              void* d_out, int out_size)
{
    const float* x     = (const float*)d_in[0];
    const float* w_q   = (const float*)d_in[1];
    const float* w_k   = (const float*)d_in[2];
    const float* w_v   = (const float*)d_in[3];
    const float* w_o   = (const float*)d_in[4];
    const float* w_ff1 = (const float*)d_in[5];
    const float* b_ff1 = (const float*)d_in[6];
    const float* w_ff2 = (const float*)d_in[7];
    const float* b_ff2 = (const float*)d_in[8];
    const float* g1    = (const float*)d_in[9];
    const float* b1    = (const float*)d_in[10];
    const float* g2    = (const float*)d_in[11];
    const float* b2    = (const float*)d_in[12];
    float* out = (float*)d_out;

    __nv_bfloat16 *xh, *xl, *wqh, *wql, *wkh, *wkl, *wvh, *wvl, *woh, *wol;
    __nv_bfloat16 *w1h, *w1l, *w2h, *w2l, *ath, *atl, *h1h, *h1l, *ffh, *ffl;
    __nv_bfloat16 *qn, *kn, *vt;
    float *q, *k, *v, *t1, *h1, *t2;
    cudaGetSymbolAddress((void**)&xh,  g_xh);  cudaGetSymbolAddress((void**)&xl,  g_xl);
    cudaGetSymbolAddress((void**)&wqh, g_wqh); cudaGetSymbolAddress((void**)&wql, g_wql);
    cudaGetSymbolAddress((void**)&wkh, g_wkh); cudaGetSymbolAddress((void**)&wkl, g_wkl);
    cudaGetSymbolAddress((void**)&wvh, g_wvh); cudaGetSymbolAddress((void**)&wvl, g_wvl);
    cudaGetSymbolAddress((void**)&woh, g_woh); cudaGetSymbolAddress((void**)&wol, g_wol);
    cudaGetSymbolAddress((void**)&w1h, g_w1h); cudaGetSymbolAddress((void**)&w1l, g_w1l);
    cudaGetSymbolAddress((void**)&w2h, g_w2h); cudaGetSymbolAddress((void**)&w2l, g_w2l);
    cudaGetSymbolAddress((void**)&ath, g_ath); cudaGetSymbolAddress((void**)&atl, g_atl);
    cudaGetSymbolAddress((void**)&h1h, g_h1h); cudaGetSymbolAddress((void**)&h1l, g_h1l);
    cudaGetSymbolAddress((void**)&ffh, g_ffh); cudaGetSymbolAddress((void**)&ffl, g_ffl);
    cudaGetSymbolAddress((void**)&qn,  g_qn);  cudaGetSymbolAddress((void**)&kn,  g_kn);
    cudaGetSymbolAddress((void**)&vt,  g_vt);
    cudaGetSymbolAddress((void**)&q,  g_q);  cudaGetSymbolAddress((void**)&k,  g_k);
    cudaGetSymbolAddress((void**)&v,  g_v);  cudaGetSymbolAddress((void**)&t1, g_t1);
    cudaGetSymbolAddress((void**)&h1, g_h1); cudaGetSymbolAddress((void**)&t2, g_t2);

    cudaFuncSetAttribute(mgemm_k<0>, cudaFuncAttributeMaxDynamicSharedMemorySize, MG_SMEM);
    cudaFuncSetAttribute(mgemm_k<1>, cudaFuncAttributeMaxDynamicSharedMemorySize, MG_SMEM);
    cudaFuncSetAttribute(mgemm_k<2>, cudaFuncAttributeMaxDynamicSharedMemorySize, MG_SMEM);
    cudaFuncSetAttribute(mgemm_k<3>, cudaFuncAttributeMaxDynamicSharedMemorySize, MG_SMEM);

    // --- input + weight prep ---
    const int n4 = MM * DDIM / 4;
    split_k<<<n4 / 256, 256>>>((const float4*)x, (__nv_bfloat162*)xh,
                               (__nv_bfloat162*)xl, n4);
    tsplit_k<<<dim3(DDIM / 32, DDIM / 32), 256>>>(w_q,   wqh, wql, DDIM, DDIM);
    tsplit_k<<<dim3(DDIM / 32, DDIM / 32), 256>>>(w_k,   wkh, wkl, DDIM, DDIM);
    tsplit_k<<<dim3(DDIM / 32, DDIM / 32), 256>>>(w_v,   wvh, wvl, DDIM, DDIM);
    tsplit_k<<<dim3(DDIM / 32, DDIM / 32), 256>>>(w_o,   woh, wol, DDIM, DDIM);
    tsplit_k<<<dim3(DFFN / 32, DDIM / 32), 256>>>(w_ff1, w1h, w1l, DDIM, DFFN);
    tsplit_k<<<dim3(DDIM / 32, DFFN / 32), 256>>>(w_ff2, w2h, w2l, DFFN, DDIM);

    const dim3 g512(DDIM / 128, MM / 128);   // (4, 128)
    const dim3 gff1(DFFN / 128, MM / 128);   // (16, 128)

    // --- Q/K/V projections (fp32 out, [16384,512] == [b,s,h,dk]) ---
    mgemm_k<0><<<g512, 256, MG_SMEM>>>(xh, xl, wqh, wql, q, MM, DDIM, DDIM,
                                       nullptr, nullptr, nullptr, nullptr);
    mgemm_k<0><<<g512, 256, MG_SMEM>>>(xh, xl, wkh, wkl, k, MM, DDIM, DDIM,
                                       nullptr, nullptr, nullptr, nullptr);
    mgemm_k<0><<<g512, 256, MG_SMEM>>>(xh, xl, wvh, wvl, v, MM, DDIM, DDIM,
                                       nullptr, nullptr, nullptr, nullptr);

    // --- normalize+convert q,k; transpose+convert v ---
    qknorm_k<<<(MM * HH) / 16, 256>>>(q, qn, MM * HH, 0.125f);
    qknorm_k<<<(MM * HH) / 16, 256>>>(k, kn, MM * HH, 1.0f);
    vtrans_k<<<dim3(SS / 64, HH, BB), 256>>>(v, vt);

    // --- flash-style HMMA cosine attention -> bf16 split output ---
    fattn_k<<<dim3(SS / 64, HH, BB), 128>>>(qn, kn, vt, ath, atl);

    // --- O-projection + residual x -> t1 ---
    mgemm_k<3><<<g512, 256, MG_SMEM>>>(ath, atl, woh, wol, t1, MM, DDIM, DDIM,
                                       nullptr, x, nullptr, nullptr);

    // --- LN1 -> h1 (fp32) + bf16 split ---
    ln_k<<<MM, 128>>>(t1, g1, b1, h1, h1h, h1l);

    // --- FFN1 + bias + relu -> bf16 split only ---
    mgemm_k<1><<<gff1, 256, MG_SMEM>>>(h1h, h1l, w1h, w1l, nullptr, MM, DFFN, DDIM,
                                       b_ff1, nullptr, ffh, ffl);

    // --- FFN2 + bias + residual h1 -> t2 ---
    mgemm_k<2><<<g512, 256, MG_SMEM>>>(ffh, ffl, w2h, w2l, t2, MM, DDIM, DFFN,
                                       b_ff2, h1, nullptr, nullptr);

    // --- LN2 -> output ---
    ln_k<<<MM, 128>>>(t2, g2, b2, out, nullptr, nullptr);
}

// round 12
// speedup vs baseline: 3.0220x; 1.1432x over previous
#include <cuda_runtime.h>
#include <cuda_bf16.h>
#include <cstdint>

// Problem constants
#define BB   32
#define SS   512
#define DDIM 512
#define HH   8
#define MM   (BB * SS)     // 16384 tokens
#define DFFN 2048

// ===========================================================================
// PTX helpers (baseline ISA only — harness compiles for compute_103, which
// rejects sm_103a-variant instructions like tcgen05/TMEM)
// ===========================================================================
__device__ __forceinline__ uint32_t smem_to_u32(const void* p) {
    uint32_t a;
    asm("{ .reg .u64 t; cvta.to.shared.u64 t, %1; cvt.u32.u64 %0, t; }"
        : "=r"(a) : "l"(p));
    return a;
}

#define CP_ASYNC16(smem, gptr) \
    asm volatile("cp.async.cg.shared.global [%0], [%1], 16;" \
        :: "r"(smem), "l"(gptr) : "memory")
#define CP_COMMIT() asm volatile("cp.async.commit_group;" ::: "memory")

#define LDSM_X4(r0, r1, r2, r3, addr) \
    asm volatile("ldmatrix.sync.aligned.m8n8.x4.shared.b16 {%0,%1,%2,%3}, [%4];" \
        : "=r"(r0), "=r"(r1), "=r"(r2), "=r"(r3) : "r"(addr))

#define MMA16816(d, a0, a1, a2, a3, b0, b1) \
    asm volatile("mma.sync.aligned.m16n8k16.row.col.f32.bf16.bf16.f32 " \
        "{%0,%1,%2,%3}, {%4,%5,%6,%7}, {%8,%9}, {%0,%1,%2,%3};" \
        : "+f"((d)[0]), "+f"((d)[1]), "+f"((d)[2]), "+f"((d)[3]) \
        : "r"(a0), "r"(a1), "r"(a2), "r"(a3), "r"(b0), "r"(b1))

__device__ __forceinline__ uint32_t pack_bf16x2(float lo, float hi) {
    __nv_bfloat162 t = __floats2bfloat162_rn(lo, hi);   // .x = lo (low half)
    return *(uint32_t*)&t;
}

// ===========================================================================
// Scratch (device globals)
// ===========================================================================
__device__ __nv_bfloat16 g_xh [MM * DDIM], g_xl [MM * DDIM];
__device__ __nv_bfloat16 g_wqkvh[3 * DDIM * DDIM], g_wqkvl[3 * DDIM * DDIM];
__device__ __nv_bfloat16 g_woh[DDIM * DDIM], g_wol[DDIM * DDIM];
__device__ __nv_bfloat16 g_w1h[DFFN * DDIM], g_w1l[DFFN * DDIM];
__device__ __nv_bfloat16 g_w2h[DDIM * DFFN], g_w2l[DDIM * DFFN];
__device__ __nv_bfloat16 g_ath[MM * DDIM], g_atl[MM * DDIM];
__device__ __nv_bfloat16 g_h1h[MM * DDIM], g_h1l[MM * DDIM];
__device__ __nv_bfloat16 g_ffh[(size_t)MM * DFFN], g_ffl[(size_t)MM * DFFN];
__device__ __nv_bfloat16 g_qn [MM * DDIM], g_kn [MM * DDIM], g_vt [MM * DDIM];
__device__ float g_qkv[(size_t)MM * 3 * DDIM];
__device__ float g_t1[MM * DDIM], g_h1[MM * DDIM], g_t2[MM * DDIM];

__device__ __forceinline__ void bsplit(float x, __nv_bfloat16& hi, __nv_bfloat16& lo) {
    hi = __float2bfloat16(x);
    lo = __float2bfloat16(x - __bfloat162float(hi));
}

// ===========================================================================
// fp32 -> bf16 hi/lo split (elementwise)
// ===========================================================================
__global__ __launch_bounds__(256)
void split_k(const float4* __restrict__ X, __nv_bfloat162* __restrict__ Hi,
             __nv_bfloat162* __restrict__ Lo, int n4)
{
    int i = blockIdx.x * 256 + threadIdx.x;
    if (i >= n4) return;
    float4 v = X[i];
    __nv_bfloat16 h0, h1, h2, h3, l0, l1, l2, l3;
    bsplit(v.x, h0, l0); bsplit(v.y, h1, l1);
    bsplit(v.z, h2, l2); bsplit(v.w, h3, l3);
    Hi[i * 2]     = __halves2bfloat162(h0, h1);
    Hi[i * 2 + 1] = __halves2bfloat162(h2, h3);
    Lo[i * 2]     = __halves2bfloat162(l0, l1);
    Lo[i * 2 + 1] = __halves2bfloat162(l2, l3);
}

// ===========================================================================
// Weight transpose + split: W[K,N] fp32 -> Thi/Tlo [N,K] bf16 (K-major)
// ===========================================================================
__global__ __launch_bounds__(256)
void tsplit_k(const float* __restrict__ W, __nv_bfloat16* __restrict__ Thi,
              __nv_bfloat16* __restrict__ Tlo, int K, int N)
{
    __shared__ float t[32][33];
    const int tx = threadIdx.x & 31, ty = threadIdx.x >> 5;
    const int n0 = blockIdx.x * 32, k0 = blockIdx.y * 32;
#pragma unroll
    for (int j = 0; j < 4; j++)
        t[ty + j * 8][tx] = W[(size_t)(k0 + ty + j * 8) * N + n0 + tx];
    __syncthreads();
#pragma unroll
    for (int j = 0; j < 4; j++) {
        const float v = t[tx][ty + j * 8];
        __nv_bfloat16 hi, lo;
        bsplit(v, hi, lo);
        const size_t o = (size_t)(n0 + ty + j * 8) * K + k0 + tx;
        Thi[o] = hi; Tlo[o] = lo;
    }
}

// ===========================================================================
// bf16-split HMMA GEMM: C[M,N] = (Ahi+Alo)[M,K] @ (Bhi+Blo)[N,K]^T
// 3-term split (hi*hi + hi*lo + lo*hi), fp32 accumulators.
// 512 threads (16 warps, 4x4 grid, warp tile m32n32), BM=BN=128, BK=32,
// 4-stage cp.async pipeline, ONE __syncthreads per k-block.
//   EPI 0: C = acc
//   EPI 1: Chi/Clo = split(relu(acc + bias))     (bf16 out only)
//   EPI 2: C = acc + bias + res
//   EPI 3: C = acc + res
// ===========================================================================
#define SROW   40                    // 80 B smem row stride, ldmatrix conflict-free
#define TILE_E (128 * SROW)
#define NSTAGE 4
static constexpr int MG_SMEM = NSTAGE * 4 * TILE_E * 2;   // 163840 B

template <int EPI>
__global__ __launch_bounds__(512, 1)
void mgemm_k(const __nv_bfloat16* __restrict__ Ahi, const __nv_bfloat16* __restrict__ Alo,
             const __nv_bfloat16* __restrict__ Bhi, const __nv_bfloat16* __restrict__ Blo,
             float* __restrict__ C, int M, int N, int K,
             const float* __restrict__ bias, const float* __restrict__ res,
             __nv_bfloat16* __restrict__ Chi, __nv_bfloat16* __restrict__ Clo)
{
    extern __shared__ __nv_bfloat16 sm[];
    const uint32_t sm0 = smem_to_u32(sm);

    const int tid  = threadIdx.x;
    const int wid  = tid >> 5, lane = tid & 31;
    const int wr   = wid >> 2, wc = wid & 3;      // warp grid 4 x 4
    const int bm   = blockIdx.y, bn = blockIdx.x;

    // cp.async mapping: 512 threads cover one 16B chunk per tile
    const int lrow = tid >> 2;            // 0..127
    const int lcg  = tid & 3;             // chunk col 0..3

    const size_t aoff = (size_t)(bm * 128 + lrow) * K + lcg * 8;
    const size_t boff = (size_t)(bn * 128 + lrow) * K + lcg * 8;
    const uint32_t thr_off = (uint32_t)(lrow * SROW + lcg * 8) * 2;

    auto issue = [&](int stg, int kb) {
        const uint32_t s = sm0 + (uint32_t)(stg * 4) * (TILE_E * 2) + thr_off;
        CP_ASYNC16(s,              Ahi + aoff + kb * 32);
        CP_ASYNC16(s + TILE_E * 2, Alo + aoff + kb * 32);
        CP_ASYNC16(s + TILE_E * 4, Bhi + boff + kb * 32);
        CP_ASYNC16(s + TILE_E * 6, Blo + boff + kb * 32);
        CP_COMMIT();
    };

    float acc[2][4][4];
#pragma unroll
    for (int i = 0; i < 2; i++)
#pragma unroll
        for (int j = 0; j < 4; j++)
#pragma unroll
            for (int l = 0; l < 4; l++) acc[i][j][l] = 0.f;

    // ldmatrix per-lane address components (verified in R6)
    const int q4     = lane >> 3;
    const int arow_l = (q4 & 1) * 8 + (lane & 7);
    const int akc_l  = (q4 >> 1) * 8;
    const int brow_l = (q4 >> 1) * 8 + (lane & 7);
    const int bkc_l  = (q4 & 1) * 8;

    auto compute = [&](int stg) {
        const uint32_t aH = sm0 + (uint32_t)(stg * 4 + 0) * (TILE_E * 2);
        const uint32_t aL = sm0 + (uint32_t)(stg * 4 + 1) * (TILE_E * 2);
        const uint32_t bH = sm0 + (uint32_t)(stg * 4 + 2) * (TILE_E * 2);
        const uint32_t bL = sm0 + (uint32_t)(stg * 4 + 3) * (TILE_E * 2);
#pragma unroll
        for (int ks = 0; ks < 2; ks++) {
            const uint32_t arow_off =
                (uint32_t)((wr * 32 + arow_l) * SROW + ks * 16 + akc_l) * 2;
            const uint32_t brow_off =
                (uint32_t)((wc * 32 + brow_l) * SROW + ks * 16 + bkc_l) * 2;

            uint32_t ah[2][4], bh[2][4];
#pragma unroll
            for (int mi = 0; mi < 2; mi++)
                LDSM_X4(ah[mi][0], ah[mi][1], ah[mi][2], ah[mi][3],
                        aH + arow_off + mi * 16 * SROW * 2);
#pragma unroll
            for (int nb = 0; nb < 2; nb++)
                LDSM_X4(bh[nb][0], bh[nb][1], bh[nb][2], bh[nb][3],
                        bH + brow_off + nb * 16 * SROW * 2);
            // term 1: hi * hi
#pragma unroll
            for (int mi = 0; mi < 2; mi++)
#pragma unroll
                for (int nb = 0; nb < 2; nb++) {
                    MMA16816(acc[mi][nb * 2 + 0],
                             ah[mi][0], ah[mi][1], ah[mi][2], ah[mi][3],
                             bh[nb][0], bh[nb][1]);
                    MMA16816(acc[mi][nb * 2 + 1],
                             ah[mi][0], ah[mi][1], ah[mi][2], ah[mi][3],
                             bh[nb][2], bh[nb][3]);
                }
            // term 2: lo * hi  (bh still live)
            {
                uint32_t al[2][4];
#pragma unroll
                for (int mi = 0; mi < 2; mi++)
                    LDSM_X4(al[mi][0], al[mi][1], al[mi][2], al[mi][3],
                            aL + arow_off + mi * 16 * SROW * 2);
#pragma unroll
                for (int mi = 0; mi < 2; mi++)
#pragma unroll
                    for (int nb = 0; nb < 2; nb++) {
                        MMA16816(acc[mi][nb * 2 + 0],
                                 al[mi][0], al[mi][1], al[mi][2], al[mi][3],
                                 bh[nb][0], bh[nb][1]);
                        MMA16816(acc[mi][nb * 2 + 1],
                                 al[mi][0], al[mi][1], al[mi][2], al[mi][3],
                                 bh[nb][2], bh[nb][3]);
                    }
            }
            // term 3: hi * lo  (ah still live)
            {
                uint32_t bl[2][4];
#pragma unroll
                for (int nb = 0; nb < 2; nb++)
                    LDSM_X4(bl[nb][0], bl[nb][1], bl[nb][2], bl[nb][3],
                            bL + brow_off + nb * 16 * SROW * 2);
#pragma unroll
                for (int mi = 0; mi < 2; mi++)
#pragma unroll
                    for (int nb = 0; nb < 2; nb++) {
                        MMA16816(acc[mi][nb * 2 + 0],
                                 ah[mi][0], ah[mi][1], ah[mi][2], ah[mi][3],
                                 bl[nb][0], bl[nb][1]);
                        MMA16816(acc[mi][nb * 2 + 1],
                                 ah[mi][0], ah[mi][1], ah[mi][2], ah[mi][3],
                                 bl[nb][2], bl[nb][3]);
                    }
            }
        }
    };

    const int nkb = K >> 5;
    // prologue: fill stages 0..NSTAGE-2
#pragma unroll
    for (int s = 0; s < NSTAGE - 1; s++) issue(s, s);

    for (int kb = 0; kb < nkb; kb++) {
        // tail-correct wait: last NSTAGE-2 iterations must drain fully
        if (kb + NSTAGE - 2 < nkb) {
            asm volatile("cp.async.wait_group 2;" ::: "memory");
        } else {
            asm volatile("cp.async.wait_group 0;" ::: "memory");
        }
        __syncthreads();                 // ONE barrier per k-block
        compute(kb & (NSTAGE - 1));
        if (kb + NSTAGE - 1 < nkb)
            issue((kb + NSTAGE - 1) & (NSTAGE - 1), kb + NSTAGE - 1);
    }

    // ---- epilogue ----
    const int r4 = lane >> 2;
    const int c2 = (lane & 3) * 2;
#pragma unroll
    for (int mi = 0; mi < 2; mi++) {
#pragma unroll
        for (int half = 0; half < 2; half++) {
            const int row = bm * 128 + wr * 32 + mi * 16 + r4 + half * 8;
#pragma unroll
            for (int ni = 0; ni < 4; ni++) {
                const int col = bn * 128 + wc * 32 + ni * 8 + c2;
                float v0 = acc[mi][ni][half * 2 + 0];
                float v1 = acc[mi][ni][half * 2 + 1];
                if (EPI == 1) {
                    v0 = fmaxf(v0 + bias[col],     0.f);
                    v1 = fmaxf(v1 + bias[col + 1], 0.f);
                    __nv_bfloat16 h0, h1, l0, l1;
                    bsplit(v0, h0, l0); bsplit(v1, h1, l1);
                    *(__nv_bfloat162*)(Chi + (size_t)row * N + col) = __halves2bfloat162(h0, h1);
                    *(__nv_bfloat162*)(Clo + (size_t)row * N + col) = __halves2bfloat162(l0, l1);
                } else {
                    if (EPI == 2) { v0 += bias[col]; v1 += bias[col + 1]; }
                    if (EPI == 2 || EPI == 3) {
                        const float2 rv = *(const float2*)(res + (size_t)row * N + col);
                        v0 += rv.x; v1 += rv.y;
                    }
                    *(float2*)(C + (size_t)row * N + col) = make_float2(v0, v1);
                }
            }
        }
    }
}

// ===========================================================================
// Fused row-normalize + bf16 convert from the fused QKV tensor.
// QKV is [MM, 1536]; logical row r: token m = r>>3, head h = r&7.
// Out[r,:] = bf16( X[m, coloff + h*64 ...] * scale / ||.|| )
// ===========================================================================
__global__ __launch_bounds__(256)
void qknorm_k(const float* __restrict__ X, __nv_bfloat16* __restrict__ Out,
              int nrows, float scale, int coloff)
{
    const int t   = threadIdx.x;
    const int grp = t >> 4;
    const int ln  = t & 15;
    const int row = blockIdx.x * 16 + grp;
    if (row >= nrows) return;
    const int m = row >> 3, hh = row & 7;
    const float4 v = *(const float4*)(X + (size_t)m * 1536 + coloff + hh * 64 + ln * 4);
    float ss = v.x * v.x + v.y * v.y + v.z * v.z + v.w * v.w;
#pragma unroll
    for (int o = 8; o > 0; o >>= 1) ss += __shfl_xor_sync(0xffffffffu, ss, o);
    const float sc = scale * rsqrtf(fmaxf(ss, 1e-24f));
    __nv_bfloat162* o2 = (__nv_bfloat162*)(Out + (size_t)row * 64 + ln * 4);
    o2[0] = __floats2bfloat162_rn(v.x * sc, v.y * sc);
    o2[1] = __floats2bfloat162_rn(v.z * sc, v.w * sc);
}

// ===========================================================================
// V transpose + convert from fused QKV: v fp32 (cols 1024..1535) -> vt bf16 [b,h,d,s]
// ===========================================================================
__global__ __launch_bounds__(256)
void vtrans_k(const float* __restrict__ QKV, __nv_bfloat16* __restrict__ Vt)
{
    __shared__ float t[64][65];
    const int tid = threadIdx.x;
    const int st = blockIdx.x;        // s-tile 0..7
    const int h  = blockIdx.y, b = blockIdx.z;
    const int r16 = tid >> 4;         // 0..15
    const int c16 = tid & 15;
#pragma unroll
    for (int it = 0; it < 4; it++) {
        const int s = it * 16 + r16;
        const float4 v4 = *(const float4*)(
            QKV + (size_t)(b * SS + st * 64 + s) * 1536 + 1024 + h * 64 + c16 * 4);
        t[s][c16 * 4 + 0] = v4.x; t[s][c16 * 4 + 1] = v4.y;
        t[s][c16 * 4 + 2] = v4.z; t[s][c16 * 4 + 3] = v4.w;
    }
    __syncthreads();
#pragma unroll
    for (int it = 0; it < 4; it++) {
        const int d = it * 16 + r16;
        const int s0 = c16 * 4;
        const size_t o = ((size_t)((b * HH + h) * 64 + d)) * SS + st * 64 + s0;
        *(__nv_bfloat162*)(Vt + o)     = __floats2bfloat162_rn(t[s0][d],     t[s0 + 1][d]);
        *(__nv_bfloat162*)(Vt + o + 2) = __floats2bfloat162_rn(t[s0 + 2][d], t[s0 + 3][d]);
    }
}

// ===========================================================================
// Flash-style HMMA cosine attention (unchanged from R7 — verified).
// ===========================================================================
#define FSR 72   // smem row stride (144B -> ldmatrix conflict-free)

__global__ __launch_bounds__(128, 4)
void fattn_k(const __nv_bfloat16* __restrict__ Qn, const __nv_bfloat16* __restrict__ Kn,
             const __nv_bfloat16* __restrict__ Vt,
             __nv_bfloat16* __restrict__ Ohi, __nv_bfloat16* __restrict__ Olo)
{
    __shared__ __nv_bfloat16 Qs[64 * FSR];
    __shared__ __nv_bfloat16 Ks[2][64 * FSR];
    __shared__ __nv_bfloat16 Vs[2][64 * FSR];

    const int tid = threadIdx.x, wid = tid >> 5, lane = tid & 31;
    const int b = blockIdx.z, h = blockIdx.y, qt = blockIdx.x;

    const int row = tid >> 1;
    const int cg  = (tid & 1) * 4;

    const size_t qbase = ((size_t)(b * SS + qt * 64 + row) * HH + h) * 64 + cg * 8;
    const size_t kbase = ((size_t)(b * SS + row) * HH + h) * 64 + cg * 8;
    const size_t vbase = ((size_t)((b * HH + h) * 64 + row)) * SS + cg * 8;
    const uint32_t thr_s = (uint32_t)(row * FSR + cg * 8) * 2;
    const uint32_t sQ  = smem_to_u32(Qs)    + thr_s;
    const uint32_t sK0 = smem_to_u32(Ks[0]) + thr_s;
    const uint32_t sV0 = smem_to_u32(Vs[0]) + thr_s;
    const uint32_t bufstep = 64 * FSR * 2;

#pragma unroll
    for (int j = 0; j < 4; j++) CP_ASYNC16(sQ + j * 16, Qn + qbase + j * 8);
#pragma unroll
    for (int j = 0; j < 4; j++) CP_ASYNC16(sK0 + j * 16, Kn + kbase + j * 8);
#pragma unroll
    for (int j = 0; j < 4; j++) CP_ASYNC16(sV0 + j * 16, Vt + vbase + j * 8);
    CP_COMMIT();
#pragma unroll
    for (int j = 0; j < 4; j++) CP_ASYNC16(sK0 + bufstep + j * 16, Kn + kbase + 32768 + j * 8);
#pragma unroll
    for (int j = 0; j < 4; j++) CP_ASYNC16(sV0 + bufstep + j * 16, Vt + vbase + 64 + j * 8);
    CP_COMMIT();

    asm volatile("cp.async.wait_group 1;" ::: "memory");
    __syncthreads();

    const int q4     = lane >> 3;
    const int arow_l = (q4 & 1) * 8 + (lane & 7);
    const int akc_l  = (q4 >> 1) * 8;
    const int brow_l = (q4 >> 1) * 8 + (lane & 7);
    const int bkc_l  = (q4 & 1) * 8;

    uint32_t qa[4][4];
    {
        const uint32_t qb = smem_to_u32(Qs);
#pragma unroll
        for (int ks = 0; ks < 4; ks++)
            LDSM_X4(qa[ks][0], qa[ks][1], qa[ks][2], qa[ks][3],
                    qb + (uint32_t)((wid * 16 + arow_l) * FSR + ks * 16 + akc_l) * 2);
    }

    float oacc[4][2][4];
#pragma unroll
    for (int i = 0; i < 4; i++)
#pragma unroll
        for (int j = 0; j < 2; j++)
#pragma unroll
            for (int l = 0; l < 4; l++) oacc[i][j][l] = 0.f;
    float lsum0 = 0.f, lsum1 = 0.f;

    for (int kt = 0; kt < 8; kt++) {
        const int cur = kt & 1;
        const uint32_t kbS = smem_to_u32(Ks[cur]);
        const uint32_t vbS = smem_to_u32(Vs[cur]);

        float sacc[4][2][4];
#pragma unroll
        for (int i = 0; i < 4; i++)
#pragma unroll
            for (int j = 0; j < 2; j++)
#pragma unroll
                for (int l = 0; l < 4; l++) sacc[i][j][l] = 0.f;
#pragma unroll
        for (int ks = 0; ks < 4; ks++) {
            uint32_t kf[4][4];
#pragma unroll
            for (int nb = 0; nb < 4; nb++)
                LDSM_X4(kf[nb][0], kf[nb][1], kf[nb][2], kf[nb][3],
                        kbS + (uint32_t)((nb * 16 + brow_l) * FSR + ks * 16 + bkc_l) * 2);
#pragma unroll
            for (int nb = 0; nb < 4; nb++) {
                MMA16816(sacc[nb][0], qa[ks][0], qa[ks][1], qa[ks][2], qa[ks][3],
                         kf[nb][0], kf[nb][1]);
                MMA16816(sacc[nb][1], qa[ks][0], qa[ks][1], qa[ks][2], qa[ks][3],
                         kf[nb][2], kf[nb][3]);
            }
        }

        uint32_t pa[4][4];
#pragma unroll
        for (int nb = 0; nb < 4; nb++) {
#pragma unroll
            for (int h2 = 0; h2 < 2; h2++)
#pragma unroll
                for (int e = 0; e < 4; e++) {
                    const float x = sacc[nb][h2][e];
                    float p = fmaf(8.3333333e-3f, x, 4.1666667e-2f);
                    p = fmaf(p, x, 0.16666667f);
                    p = fmaf(p, x, 0.5f);
                    p = fmaf(p, x, 1.0f);
                    p = fmaf(p, x, 1.0f);
                    sacc[nb][h2][e] = p;
                }
            lsum0 += sacc[nb][0][0] + sacc[nb][0][1] + sacc[nb][1][0] + sacc[nb][1][1];
            lsum1 += sacc[nb][0][2] + sacc[nb][0][3] + sacc[nb][1][2] + sacc[nb][1][3];
            pa[nb][0] = pack_bf16x2(sacc[nb][0][0], sacc[nb][0][1]);
            pa[nb][1] = pack_bf16x2(sacc[nb][0][2], sacc[nb][0][3]);
            pa[nb][2] = pack_bf16x2(sacc[nb][1][0], sacc[nb][1][1]);
            pa[nb][3] = pack_bf16x2(sacc[nb][1][2], sacc[nb][1][3]);
        }

#pragma unroll
        for (int ks2 = 0; ks2 < 4; ks2++) {
            uint32_t vf[4][4];
#pragma unroll
            for (int db = 0; db < 4; db++)
                LDSM_X4(vf[db][0], vf[db][1], vf[db][2], vf[db][3],
                        vbS + (uint32_t)((db * 16 + brow_l) * FSR + ks2 * 16 + bkc_l) * 2);
#pragma unroll
            for (int db = 0; db < 4; db++) {
                MMA16816(oacc[db][0], pa[ks2][0], pa[ks2][1], pa[ks2][2], pa[ks2][3],
                         vf[db][0], vf[db][1]);
                MMA16816(oacc[db][1], pa[ks2][0], pa[ks2][1], pa[ks2][2], pa[ks2][3],
                         vf[db][2], vf[db][3]);
            }
        }

        if (kt < 7) {
            __syncthreads();
            if (kt + 2 < 8) {
                const size_t ko = kbase + (size_t)(kt + 2) * 32768;
                const size_t vo = vbase + (kt + 2) * 64;
                const uint32_t sk = sK0 + cur * bufstep;
                const uint32_t sv = sV0 + cur * bufstep;
#pragma unroll
                for (int j = 0; j < 4; j++) CP_ASYNC16(sk + j * 16, Kn + ko + j * 8);
#pragma unroll
                for (int j = 0; j < 4; j++) CP_ASYNC16(sv + j * 16, Vt + vo + j * 8);
                CP_COMMIT();
                asm volatile("cp.async.wait_group 1;" ::: "memory");
            } else {
                asm volatile("cp.async.wait_group 0;" ::: "memory");
            }
            __syncthreads();
        }
    }

    lsum0 += __shfl_xor_sync(0xffffffffu, lsum0, 1);
    lsum0 += __shfl_xor_sync(0xffffffffu, lsum0, 2);
    lsum1 += __shfl_xor_sync(0xffffffffu, lsum1, 1);
    lsum1 += __shfl_xor_sync(0xffffffffu, lsum1, 2);
    const float inv0 = 1.f / lsum0;
    const float inv1 = 1.f / lsum1;

    const int r4 = lane >> 2;
    const int c2 = (lane & 3) * 2;
    const int s0 = qt * 64 + wid * 16 + r4;
#pragma unroll
    for (int db = 0; db < 4; db++) {
#pragma unroll
        for (int h2 = 0; h2 < 2; h2++) {
            const int d = db * 16 + h2 * 8 + c2;
            {
                const float v0 = oacc[db][h2][0] * inv0;
                const float v1 = oacc[db][h2][1] * inv0;
                __nv_bfloat16 hh0, hh1, ll0, ll1;
                bsplit(v0, hh0, ll0); bsplit(v1, hh1, ll1);
                const size_t o = ((size_t)(b * SS + s0) * HH + h) * 64 + d;
                *(__nv_bfloat162*)(Ohi + o) = __halves2bfloat162(hh0, hh1);
                *(__nv_bfloat162*)(Olo + o) = __halves2bfloat162(ll0, ll1);
            }
            {
                const float v0 = oacc[db][h2][2] * inv1;
                const float v1 = oacc[db][h2][3] * inv1;
                __nv_bfloat16 hh0, hh1, ll0, ll1;
                bsplit(v0, hh0, ll0); bsplit(v1, hh1, ll1);
                const size_t o = ((size_t)(b * SS + s0 + 8) * HH + h) * 64 + d;
                *(__nv_bfloat162*)(Ohi + o) = __halves2bfloat162(hh0, hh1);
                *(__nv_bfloat162*)(Olo + o) = __halves2bfloat162(ll0, ll1);
            }
        }
    }
}

// ===========================================================================
// LayerNorm over last dim (512), optional fused bf16 hi/lo split output.
// ===========================================================================
__global__ __launch_bounds__(128)
void ln_k(const float* __restrict__ X, const float* __restrict__ gamma,
          const float* __restrict__ beta, float* __restrict__ out,
          __nv_bfloat16* __restrict__ hi, __nv_bfloat16* __restrict__ lo)
{
    __shared__ float s_sum[4], s_ss[4];
    const int tid = threadIdx.x;
    const size_t row = blockIdx.x;

    const float4 v = *(const float4*)(X + row * 512 + tid * 4);
    float sum = v.x + v.y + v.z + v.w;
    float ss  = v.x * v.x + v.y * v.y + v.z * v.z + v.w * v.w;
#pragma unroll
    for (int o = 16; o > 0; o >>= 1) {
        sum += __shfl_xor_sync(0xffffffffu, sum, o);
        ss  += __shfl_xor_sync(0xffffffffu, ss,  o);
    }
    if ((tid & 31) == 0) { s_sum[tid >> 5] = sum; s_ss[tid >> 5] = ss; }
    __syncthreads();
    sum = s_sum[0] + s_sum[1] + s_sum[2] + s_sum[3];
    ss  = s_ss[0]  + s_ss[1]  + s_ss[2]  + s_ss[3];

    const float mean = sum * (1.f / 512.f);
    const float var  = ss * (1.f / 512.f) - mean * mean;
    const float rstd = rsqrtf(var + 1e-5f);

    const int c = tid * 4;
    const float4 gv = *(const float4*)(gamma + c);
    const float4 bv = *(const float4*)(beta + c);
    float4 o4;
    o4.x = (v.x - mean) * rstd * gv.x + bv.x;
    o4.y = (v.y - mean) * rstd * gv.y + bv.y;
    o4.z = (v.z - mean) * rstd * gv.z + bv.z;
    o4.w = (v.w - mean) * rstd * gv.w + bv.w;
    *(float4*)(out + row * 512 + c) = o4;

    if (hi != nullptr) {
        __nv_bfloat16 h0, h1, h2, h3, l0, l1, l2, l3;
        bsplit(o4.x, h0, l0); bsplit(o4.y, h1, l1);
        bsplit(o4.z, h2, l2); bsplit(o4.w, h3, l3);
        const size_t i2 = row * 256 + tid * 2;
        ((__nv_bfloat162*)hi)[i2]     = __halves2bfloat162(h0, h1);
        ((__nv_bfloat162*)hi)[i2 + 1] = __halves2bfloat162(h2, h3);
        ((__nv_bfloat162*)lo)[i2]     = __halves2bfloat162(l0, l1);
        ((__nv_bfloat162*)lo)[i2 + 1] = __halves2bfloat162(l2, l3);
    }
}

// ===========================================================================
// Launch sequence
// ===========================================================================
extern "C" void kernel_launch(void* const* d_in, const int* in_sizes, int n_in,
                              void* d_out, int out_size)
{
    const float* x     = (const float*)d_in[0];
    const float* w_q   = (const float*)d_in[1];
    const float* w_k   = (const float*)d_in[2];
    const float* w_v   = (const float*)d_in[3];
    const float* w_o   = (const float*)d_in[4];
    const float* w_ff1 = (const float*)d_in[5];
    const float* b_ff1 = (const float*)d_in[6];
    const float* w_ff2 = (const float*)d_in[7];
    const float* b_ff2 = (const float*)d_in[8];
    const float* g1    = (const float*)d_in[9];
    const float* b1    = (const float*)d_in[10];
    const float* g2    = (const float*)d_in[11];
    const float* b2    = (const float*)d_in[12];
    float* out = (float*)d_out;

    __nv_bfloat16 *xh, *xl, *wqkvh, *wqkvl, *woh, *wol;
    __nv_bfloat16 *w1h, *w1l, *w2h, *w2l, *ath, *atl, *h1h, *h1l, *ffh, *ffl;
    __nv_bfloat16 *qn, *kn, *vt;
    float *qkv, *t1, *h1, *t2;
    cudaGetSymbolAddress((void**)&xh,  g_xh);  cudaGetSymbolAddress((void**)&xl,  g_xl);
    cudaGetSymbolAddress((void**)&wqkvh, g_wqkvh); cudaGetSymbolAddress((void**)&wqkvl, g_wqkvl);
    cudaGetSymbolAddress((void**)&woh, g_woh); cudaGetSymbolAddress((void**)&wol, g_wol);
    cudaGetSymbolAddress((void**)&w1h, g_w1h); cudaGetSymbolAddress((void**)&w1l, g_w1l);
    cudaGetSymbolAddress((void**)&w2h, g_w2h); cudaGetSymbolAddress((void**)&w2l, g_w2l);
    cudaGetSymbolAddress((void**)&ath, g_ath); cudaGetSymbolAddress((void**)&atl, g_atl);
    cudaGetSymbolAddress((void**)&h1h, g_h1h); cudaGetSymbolAddress((void**)&h1l, g_h1l);
    cudaGetSymbolAddress((void**)&ffh, g_ffh); cudaGetSymbolAddress((void**)&ffl, g_ffl);
    cudaGetSymbolAddress((void**)&qn,  g_qn);  cudaGetSymbolAddress((void**)&kn,  g_kn);
    cudaGetSymbolAddress((void**)&vt,  g_vt);
    cudaGetSymbolAddress((void**)&qkv, g_qkv);
    cudaGetSymbolAddress((void**)&t1, g_t1);
    cudaGetSymbolAddress((void**)&h1, g_h1); cudaGetSymbolAddress((void**)&t2, g_t2);

    cudaFuncSetAttribute(mgemm_k<0>, cudaFuncAttributeMaxDynamicSharedMemorySize, MG_SMEM);
    cudaFuncSetAttribute(mgemm_k<1>, cudaFuncAttributeMaxDynamicSharedMemorySize, MG_SMEM);
    cudaFuncSetAttribute(mgemm_k<2>, cudaFuncAttributeMaxDynamicSharedMemorySize, MG_SMEM);
    cudaFuncSetAttribute(mgemm_k<3>, cudaFuncAttributeMaxDynamicSharedMemorySize, MG_SMEM);

    // --- input + weight prep (QKV weights concatenated -> [1536, 512]) ---
    const int n4 = MM * DDIM / 4;
    split_k<<<n4 / 256, 256>>>((const float4*)x, (__nv_bfloat162*)xh,
                               (__nv_bfloat162*)xl, n4);
    tsplit_k<<<dim3(DDIM / 32, DDIM / 32), 256>>>(w_q, wqkvh,                 wqkvl,                 DDIM, DDIM);
    tsplit_k<<<dim3(DDIM / 32, DDIM / 32), 256>>>(w_k, wqkvh + DDIM * DDIM,   wqkvl + DDIM * DDIM,   DDIM, DDIM);
    tsplit_k<<<dim3(DDIM / 32, DDIM / 32), 256>>>(w_v, wqkvh + 2 * DDIM * DDIM, wqkvl + 2 * DDIM * DDIM, DDIM, DDIM);
    tsplit_k<<<dim3(DDIM / 32, DDIM / 32), 256>>>(w_o,   woh, wol, DDIM, DDIM);
    tsplit_k<<<dim3(DFFN / 32, DDIM / 32), 256>>>(w_ff1, w1h, w1l, DDIM, DFFN);
    tsplit_k<<<dim3(DDIM / 32, DFFN / 32), 256>>>(w_ff2, w2h, w2l, DFFN, DDIM);

    const dim3 gqkv(3 * DDIM / 128, MM / 128);  // (12, 128)
    const dim3 g512(DDIM / 128, MM / 128);      // (4, 128)
    const dim3 gff1(DFFN / 128, MM / 128);      // (16, 128)

    // --- fused QKV projection (fp32 out, [16384, 1536]) ---
    mgemm_k<0><<<gqkv, 512, MG_SMEM>>>(xh, xl, wqkvh, wqkvl, qkv, MM, 3 * DDIM, DDIM,
                                       nullptr, nullptr, nullptr, nullptr);

    // --- normalize+convert q,k; transpose+convert v ---
    qknorm_k<<<(MM * HH) / 16, 256>>>(qkv, qn, MM * HH, 0.125f, 0);
    qknorm_k<<<(MM * HH) / 16, 256>>>(qkv, kn, MM * HH, 1.0f,   512);
    vtrans_k<<<dim3(SS / 64, HH, BB), 256>>>(qkv, vt);

    // --- flash-style HMMA cosine attention -> bf16 split output ---
    fattn_k<<<dim3(SS / 64, HH, BB), 128>>>(qn, kn, vt, ath, atl);

    // --- O-projection + residual x -> t1 ---
    mgemm_k<3><<<g512, 512, MG_SMEM>>>(ath, atl, woh, wol, t1, MM, DDIM, DDIM,
                                       nullptr, x, nullptr, nullptr);

    // --- LN1 -> h1 (fp32) + bf16 split ---
    ln_k<<<MM, 128>>>(t1, g1, b1, h1, h1h, h1l);

    // --- FFN1 + bias + relu -> bf16 split only ---
    mgemm_k<1><<<gff1, 512, MG_SMEM>>>(h1h, h1l, w1h, w1l, nullptr, MM, DFFN, DDIM,
                                       b_ff1, nullptr, ffh, ffl);

    // --- FFN2 + bias + residual h1 -> t2 ---
    mgemm_k<2><<<g512, 512, MG_SMEM>>>(ffh, ffl, w2h, w2l, t2, MM, DDIM, DFFN,
                                       b_ff2, h1, nullptr, nullptr);

    // --- LN2 -> output ---
    ln_k<<<MM, 128>>>(t2, g2, b2, out, nullptr, nullptr);
}